// round 8
// baseline (speedup 1.0000x reference)
#include <cuda_runtime.h>
#include <cuda_bf16.h>
#include <math.h>
#include <cstdint>

#define NN 50000
#define EE 800000
#define GG 512
#define HH 128
#define LL 3
#define OUTC 10
#define NHTOT (NN * HH)
#define HSQ (HH * HH)
#define NB ((NN + 255) / 256)
#define KBIG 512
#define NP 50176

// ---------------- scratch (device globals) ----------------------------------
__device__ float  d_bufA[NHTOT];
__device__ float  d_bufB[NHTOT];
__device__ float  d_kc[NN];
__device__ float  d_rs[NN];
__device__ float  d_rdeg[NN];
__device__ int    d_rp[NN + 1];
__device__ int    d_cnt[NN];
__device__ int    d_bsum[NB];
__device__ int    d_colsrc[EE];
__device__ float  d_reps[(LL + 1) * GG * HH];
__device__ __nv_bfloat16 d_hhi[NP * HH], d_hlo[NP * HH];     // h (or x) split
__device__ __nv_bfloat16 d_shi[NP * HH], d_slo[NP * HH];     // s_agg split
__device__ __nv_bfloat16 d_srhi[NP * HH], d_srlo[NP * HH];   // s_agg*rdeg split
__device__ __nv_bfloat16 d_ghi[NP * HH], d_glo[NP * HH];     // g_agg split
__device__ __nv_bfloat16 d_Bchi[KBIG * HH];                  // combined B [n][k] hi
__device__ __nv_bfloat16 d_Bclo[KBIG * HH];
__device__ __nv_bfloat16 d_B1hi[HSQ];
__device__ __nv_bfloat16 d_B1lo[HSQ];
__device__ int    d_gs[GG + 1];
__device__ float  d_naa[LL * 4];
__device__ float  d_pa[LL * 3];
__device__ float  d_roa[(LL + 1) * 3];
__device__ float  d_laa[3];
__device__ double d_stats[2];

__device__ __forceinline__ float eluf(float x) { return x > 0.f ? x : expm1f(x); }

__device__ __forceinline__ uint32_t smem_u32(const void* p) {
    uint32_t a;
    asm("{ .reg .u64 t; cvta.to.shared.u64 t, %1; cvt.u32.u64 %0, t; }" : "=r"(a) : "l"(p));
    return a;
}

__device__ __forceinline__ void ldm_x4(uint32_t r[4], uint32_t addr) {
    asm volatile("ldmatrix.sync.aligned.m8n8.x4.shared.b16 {%0,%1,%2,%3}, [%4];"
                 : "=r"(r[0]), "=r"(r[1]), "=r"(r[2]), "=r"(r[3]) : "r"(addr));
}

__device__ __forceinline__ void mma_bf16(float c[4], const uint32_t a[4],
                                         uint32_t b0, uint32_t b1) {
    asm volatile(
        "mma.sync.aligned.m16n8k16.row.col.f32.bf16.bf16.f32 "
        "{%0,%1,%2,%3},{%4,%5,%6,%7},{%8,%9},{%0,%1,%2,%3};"
        : "+f"(c[0]), "+f"(c[1]), "+f"(c[2]), "+f"(c[3])
        : "r"(a[0]), "r"(a[1]), "r"(a[2]), "r"(a[3]), "r"(b0), "r"(b1));
}

#define CP_ASYNC16(dst, src) asm volatile("cp.async.cg.shared.global [%0], [%1], 16;" :: "r"(dst), "l"(src))
#define CP_COMMIT()          asm volatile("cp.async.commit_group;")
#define CP_WAIT(n)           asm volatile("cp.async.wait_group %0;" :: "n"(n))

// 64B-row smem tile (32 bf16/row), XOR swizzle: conflict-free ldmatrix.
// NOTE: linear in col bits -> addr(k0+16) = addr(k0) ^ 32.
__device__ __forceinline__ uint32_t swz32(int row, int col) {
    return (uint32_t)(row * 64 + ((((col >> 3) ^ ((row >> 1) & 3))) << 4));
}

__device__ __forceinline__ void split_store4(__nv_bfloat16* hi, __nv_bfloat16* lo,
                                             size_t idx, float4 v) {
    __nv_bfloat162 h0 = __floats2bfloat162_rn(v.x, v.y);
    __nv_bfloat162 h1 = __floats2bfloat162_rn(v.z, v.w);
    float2 f0 = __bfloat1622float2(h0), f1 = __bfloat1622float2(h1);
    *(__nv_bfloat162*)&hi[idx]     = h0;
    *(__nv_bfloat162*)&hi[idx + 2] = h1;
    *(__nv_bfloat162*)&lo[idx]     = __floats2bfloat162_rn(v.x - f0.x, v.y - f0.y);
    *(__nv_bfloat162*)&lo[idx + 2] = __floats2bfloat162_rn(v.z - f1.x, v.w - f1.y);
}

// stage: AHI(8K) ALO(8K) BHI(8K) BLO(8K) = 32KB; 3 stages = 96KB
#define STG_SZ   32768
#define OFF_ALO  8192
#define OFF_BHI  16384
#define OFF_BLO  24576
#define SM_TOTAL 98304

__device__ __forceinline__ void load_stage(
    uint32_t base, const __nv_bfloat16* ah, const __nv_bfloat16* al,
    const __nv_bfloat16* bh, const __nv_bfloat16* bl, const uint32_t st_d[2]) {
#pragma unroll
    for (int j = 0; j < 2; j++) {
        uint32_t d = base + st_d[j];
        CP_ASYNC16(d,           ah + j * 8);
        CP_ASYNC16(d + OFF_ALO, al + j * 8);
        CP_ASYNC16(d + OFF_BHI, bh + j * 8);
        CP_ASYNC16(d + OFF_BLO, bl + j * 8);
    }
    CP_COMMIT();
}

// addresses precomputed: aoff[4], boff[2] relative to stage base; ks flips bit5
__device__ __forceinline__ void compute_slice(float (&acc)[4][4][4], uint32_t base,
                                              const uint32_t aoff[4], const uint32_t boff[2]) {
#pragma unroll
    for (int ks = 0; ks < 2; ks++) {
        const uint32_t kx = ks * 32;
        uint32_t bhm[2][4], blm[2][4];
#pragma unroll
        for (int np = 0; np < 2; np++) {
            uint32_t ad = base + (boff[np] ^ kx);
            ldm_x4(bhm[np], ad + OFF_BHI);
            ldm_x4(blm[np], ad + OFF_BLO);
        }
#pragma unroll
        for (int mt = 0; mt < 4; mt++) {
            uint32_t ad = base + (aoff[mt] ^ kx);
            uint32_t ah[4], al[4];
            ldm_x4(ah, ad);
            ldm_x4(al, ad + OFF_ALO);
#pragma unroll
            for (int nt = 0; nt < 4; nt++) {
                int np = nt >> 1, sel = nt & 1;
                uint32_t b0h = sel ? bhm[np][1] : bhm[np][0];
                uint32_t b1h = sel ? bhm[np][3] : bhm[np][2];
                uint32_t b0l = sel ? blm[np][1] : blm[np][0];
                uint32_t b1l = sel ? blm[np][3] : blm[np][2];
                mma_bf16(acc[mt][nt], ah, b0h, b1h);
                mma_bf16(acc[mt][nt], al, b0h, b1h);
                mma_bf16(acc[mt][nt], ah, b0l, b1l);
            }
        }
    }
}

// ---------------- tensor-core GEMM ------------------------------------------
// NSLICES = K/32. chunk = slice>>2: 0->a0(h), 1->a1(s), 2->a2(sr), 3->a3(g)
// MODE 0: bias+elu, writes C + split Chi/Clo    MODE 1: elu + LN stats
template <int NSLICES, int MODE>
__global__ void __launch_bounds__(256, 2) gemm_mma(
    const __nv_bfloat16* __restrict__ a0h, const __nv_bfloat16* __restrict__ a0l,
    const __nv_bfloat16* __restrict__ a1h, const __nv_bfloat16* __restrict__ a1l,
    const __nv_bfloat16* __restrict__ a2h, const __nv_bfloat16* __restrict__ a2l,
    const __nv_bfloat16* __restrict__ a3h, const __nv_bfloat16* __restrict__ a3l,
    const __nv_bfloat16* __restrict__ Bh, const __nv_bfloat16* __restrict__ Bl,
    float* __restrict__ C, __nv_bfloat16* __restrict__ Chi, __nv_bfloat16* __restrict__ Clo,
    const float* __restrict__ bias) {
    extern __shared__ char smem[];
    uint32_t sb = smem_u32(smem);
    const int tid = threadIdx.x;
    const int wid = tid >> 5, lane = tid & 31;
    const int warp_m = wid & 1, warp_n = wid >> 1;
    const int bm = blockIdx.x * 128;
    const int KB = NSLICES * 32;

    const int lrow = tid >> 1;
    const int lcol = (tid & 1) * 16;
    const size_t arow = (size_t)(bm + lrow) * HH;
    const size_t brow = (size_t)lrow * KB;

    // precomputed smem offsets
    uint32_t st_d[2];
    st_d[0] = swz32(lrow, lcol);
    st_d[1] = swz32(lrow, lcol + 8);
    const int lr = lane & 15, lg2 = (lane >> 4) * 8;
    const int m_base = warp_m * 64;
    const int n_base = warp_n * 32;
    uint32_t aoff[4], boff[2];
#pragma unroll
    for (int mt = 0; mt < 4; mt++) aoff[mt] = sb + swz32(m_base + mt * 16 + lr, lg2);
#pragma unroll
    for (int np = 0; np < 2; np++) boff[np] = sb + swz32(n_base + np * 16 + lr, lg2);

    float acc[4][4][4];
#pragma unroll
    for (int i = 0; i < 4; i++)
#pragma unroll
        for (int j = 0; j < 4; j++)
#pragma unroll
            for (int q = 0; q < 4; q++) acc[i][j][q] = 0.f;

#pragma unroll
    for (int pf = 0; pf < 2; pf++) {
        const int chunk = pf >> 2, koff = (pf & 3) * 32;
        const __nv_bfloat16* ah = (chunk == 0) ? a0h : (chunk == 1) ? a1h : (chunk == 2) ? a2h : a3h;
        const __nv_bfloat16* al = (chunk == 0) ? a0l : (chunk == 1) ? a1l : (chunk == 2) ? a2l : a3l;
        load_stage(sb + pf * STG_SZ, ah + arow + koff + lcol, al + arow + koff + lcol,
                   Bh + brow + pf * 32 + lcol, Bl + brow + pf * 32 + lcol, st_d);
    }

#pragma unroll
    for (int s = 0; s < NSLICES; s++) {
        if (s + 2 < NSLICES) {
            const int sn = s + 2;
            const int chunk = sn >> 2, koff = (sn & 3) * 32;
            const __nv_bfloat16* ah = (chunk == 0) ? a0h : (chunk == 1) ? a1h : (chunk == 2) ? a2h : a3h;
            const __nv_bfloat16* al = (chunk == 0) ? a0l : (chunk == 1) ? a1l : (chunk == 2) ? a2l : a3l;
            load_stage(sb + (sn % 3) * STG_SZ, ah + arow + koff + lcol, al + arow + koff + lcol,
                       Bh + brow + sn * 32 + lcol, Bl + brow + sn * 32 + lcol, st_d);
            CP_WAIT(2);
        } else if (s + 2 == NSLICES) {
            CP_WAIT(1);
        } else {
            CP_WAIT(0);
        }
        __syncthreads();
        compute_slice(acc, (uint32_t)((s % 3) * STG_SZ), aoff, boff);
        __syncthreads();
    }

    // ---- epilogue
    float lsum = 0.f, lsq = 0.f;
    int rq = lane >> 2, cq = (lane & 3) * 2;
#pragma unroll
    for (int mt = 0; mt < 4; mt++) {
#pragma unroll
        for (int half = 0; half < 2; half++) {
            int gm = bm + m_base + mt * 16 + rq + half * 8;
            if (gm >= NN) continue;
#pragma unroll
            for (int nt = 0; nt < 4; nt++) {
                int col = n_base + nt * 8 + cq;
                float v0 = acc[mt][nt][half * 2];
                float v1 = acc[mt][nt][half * 2 + 1];
                if (MODE == 0) {
                    v0 = eluf(v0 + bias[col]);
                    v1 = eluf(v1 + bias[col + 1]);
                    __nv_bfloat162 h = __floats2bfloat162_rn(v0, v1);
                    float2 hf = __bfloat1622float2(h);
                    *(__nv_bfloat162*)&Chi[(size_t)gm * HH + col] = h;
                    *(__nv_bfloat162*)&Clo[(size_t)gm * HH + col] =
                        __floats2bfloat162_rn(v0 - hf.x, v1 - hf.y);
                } else {
                    v0 = eluf(v0); v1 = eluf(v1);
                    lsum += v0 + v1;
                    lsq = fmaf(v0, v0, lsq); lsq = fmaf(v1, v1, lsq);
                }
                *(float2*)&C[(size_t)gm * HH + col] = make_float2(v0, v1);
            }
        }
    }
    if (MODE == 1) {
        double ds = (double)lsum, dq = (double)lsq;
#pragma unroll
        for (int o = 16; o; o >>= 1) {
            ds += __shfl_down_sync(0xffffffffu, ds, o);
            dq += __shfl_down_sync(0xffffffffu, dq, o);
        }
        __shared__ double ssum[8], ssq[8];
        if (lane == 0) { ssum[wid] = ds; ssq[wid] = dq; }
        __syncthreads();
        if (tid == 0) {
            double a = 0.0, b = 0.0;
#pragma unroll
            for (int i = 0; i < 8; i++) { a += ssum[i]; b += ssq[i]; }
            atomicAdd(&d_stats[0], a);
            atomicAdd(&d_stats[1], b);
        }
    }
}

// ---------------- setup ------------------------------------------------------
__device__ void softmax_n(const float* in, float* out, int n) {
    float m = in[0];
    for (int i = 1; i < n; i++) m = fmaxf(m, in[i]);
    float s = 0.f;
    for (int i = 0; i < n; i++) { out[i] = expf(in[i] - m); s += out[i]; }
    float inv = 1.f / s;
    for (int i = 0; i < n; i++) out[i] *= inv;
}

__global__ void setup_kernel(const int* __restrict__ batch,
                             const float* __restrict__ na, const float* __restrict__ pl,
                             const float* __restrict__ ro, const float* __restrict__ la) {
    int i = blockIdx.x * blockDim.x + threadIdx.x;
    if (i <= GG) {
        int lo = 0, hi = NN;
        while (lo < hi) { int mid = (lo + hi) >> 1; if (batch[mid] < i) lo = mid + 1; else hi = mid; }
        d_gs[i] = lo;
    }
    if (i < NN) { d_kc[i] = 1.f; d_cnt[i] = 0; }
    if (i == 0) {
        for (int l = 0; l < LL; l++) softmax_n(na + l * 4, d_naa + l * 4, 4);
        for (int l = 0; l < LL; l++) softmax_n(pl + l * 3, d_pa + l * 3, 3);
        for (int l = 0; l < LL + 1; l++) softmax_n(ro + l * 3, d_roa + l * 3, 3);
        softmax_n(la, d_laa, 3);
    }
}

__global__ void convert_kernel(const float* __restrict__ x, const float* __restrict__ W) {
    int idx = blockIdx.x * blockDim.x + threadIdx.x;
    if (idx < NHTOT) {
        float v = x[idx];
        __nv_bfloat16 h = __float2bfloat16(v);
        d_hhi[idx] = h;
        d_hlo[idx] = __float2bfloat16(v - __bfloat162float(h));
    } else if (idx < NHTOT + HSQ) {
        int i = idx - NHTOT;
        int k = i >> 7, n = i & 127;
        float v = W[k * HH + n];
        __nv_bfloat16 h = __float2bfloat16(v);
        d_B1hi[n * HH + k] = h;
        d_B1lo[n * HH + k] = __float2bfloat16(v - __bfloat162float(h));
    }
}

__global__ void csr_count(const int* __restrict__ ei) {
    int e = blockIdx.x * blockDim.x + threadIdx.x;
    if (e >= EE) return;
    atomicAdd(&d_cnt[ei[EE + e]], 1);
}

__global__ void scan1() {
    __shared__ int sh[256];
    int i = blockIdx.x * 256 + threadIdx.x;
    int v = (i < NN) ? d_cnt[i] : 0;
    sh[threadIdx.x] = v;
    __syncthreads();
#pragma unroll
    for (int d = 1; d < 256; d <<= 1) {
        int t = (threadIdx.x >= d) ? sh[threadIdx.x - d] : 0;
        __syncthreads();
        sh[threadIdx.x] += t;
        __syncthreads();
    }
    if (i < NN) d_rp[i + 1] = sh[threadIdx.x];
    if (threadIdx.x == 255) d_bsum[blockIdx.x] = sh[255];
}

__global__ void scan2() {
    __shared__ int sh[256];
    int t = threadIdx.x;
    int v = (t < NB) ? d_bsum[t] : 0;
    sh[t] = v;
    __syncthreads();
#pragma unroll
    for (int d = 1; d < 256; d <<= 1) {
        int tv = (t >= d) ? sh[t - d] : 0;
        __syncthreads();
        sh[t] += tv;
        __syncthreads();
    }
    if (t < NB) d_bsum[t] = sh[t] - v;
}

__global__ void scan3() {
    int i = blockIdx.x * 256 + threadIdx.x;
    if (i < NN) d_rp[i + 1] += d_bsum[blockIdx.x];
    if (i == 0) d_rp[0] = 0;
}

__global__ void csr_fill(const int* __restrict__ ei) {
    int e = blockIdx.x * blockDim.x + threadIdx.x;
    if (e >= EE) return;
    int d = ei[EE + e];
    int old = atomicSub(&d_cnt[d], 1);
    d_colsrc[d_rp[d] + old - 1] = ei[e];
}

// combine_W + deg + stats zero
__global__ void combine_deg(const float* __restrict__ W, const float* __restrict__ na) {
    int idx = blockIdx.x * blockDim.x + threadIdx.x;
    if (idx == 0) { d_stats[0] = 0.0; d_stats[1] = 0.0; }
    if (idx < 4 * HSQ) {
        int k = idx >> 7, n = idx & 127;
        int p = k >> 7, kk = k & 127;
        int widx = kk * HH + n;
        float a0 = na[0], a1 = na[1], a2 = na[2], a3 = na[3];
        float v;
        if (p == 0)      v = a1 * W[2 * HSQ + widx] + a2 * W[3 * HSQ + widx] + a3 * W[4 * HSQ + widx];
        else if (p == 1) v = a2 * W[3 * HSQ + widx] + a3 * W[5 * HSQ + widx];  // x s_agg
        else if (p == 2) v = a1 * W[1 * HSQ + widx];                            // x s_agg*rdeg
        else             v = a0 * W[widx];                                      // x g_agg
        __nv_bfloat16 h = __float2bfloat16(v);
        d_Bchi[(size_t)n * KBIG + k] = h;
        d_Bclo[(size_t)n * KBIG + k] = __float2bfloat16(v - __bfloat162float(h));
    } else {
        int n = idx - 4 * HSQ;
        if (n < NN) {
            float kcn = d_kc[n];
            float s = kcn;
            int b = d_rp[n], e = d_rp[n + 1];
            for (int p = b; p < e; p++) s += d_kc[d_colsrc[p]];
            float dg = fmaxf(kcn * s, 1e-6f);
            d_rdeg[n] = 1.f / dg;
            d_rs[n] = rsqrtf(dg);
        }
    }
}

// ---------------- gather aggregation ----------------------------------------
__global__ void aggregate_kernel(const float* __restrict__ h) {
    int gw = (blockIdx.x * blockDim.x + threadIdx.x) >> 5;
    int lane = threadIdx.x & 31;
    if (gw >= NN) return;
    float kcd = d_kc[gw];
    float rsd = d_rs[gw];
    float rdg = d_rdeg[gw];
    const float4* h4 = (const float4*)h;
    float4 hv = h4[(size_t)gw * 32 + lane];
    float wg = kcd * rsd;
    float4 as = {hv.x * kcd, hv.y * kcd, hv.z * kcd, hv.w * kcd};
    float4 ag = {hv.x * wg, hv.y * wg, hv.z * wg, hv.w * wg};
    int beg = d_rp[gw], end = d_rp[gw + 1];
    for (int p = beg; p < end; p++) {
        int s = d_colsrc[p];
        float w1 = d_kc[s];
        if (w1 != 0.f) {
            float rv = d_rs[s];
            float4 hs = h4[(size_t)s * 32 + lane];
            as.x += hs.x; as.y += hs.y; as.z += hs.z; as.w += hs.w;
            ag.x = fmaf(hs.x, rv, ag.x); ag.y = fmaf(hs.y, rv, ag.y);
            ag.z = fmaf(hs.z, rv, ag.z); ag.w = fmaf(hs.w, rv, ag.w);
        }
    }
    float fg = kcd * rsd;
    as.x *= kcd; as.y *= kcd; as.z *= kcd; as.w *= kcd;
    ag.x *= fg;  ag.y *= fg;  ag.z *= fg;  ag.w *= fg;
    float4 asr = {as.x * rdg, as.y * rdg, as.z * rdg, as.w * rdg};
    size_t idx = (size_t)gw * HH + lane * 4;
    split_store4(d_shi, d_slo, idx, as);
    split_store4(d_srhi, d_srlo, idx, asr);
    split_store4(d_ghi, d_glo, idx, ag);
}

// ---------------- layernorm + gate + pool -----------------------------------
__global__ void gate_kernel(float* __restrict__ h, const float* __restrict__ p0,
                            const float* __restrict__ pa) {
    int gw = (blockIdx.x * blockDim.x + threadIdx.x) >> 5;
    int lane = threadIdx.x & 31;
    if (gw >= NN) return;
    const double invc = 1.0 / ((double)NN * (double)HH);
    double md = d_stats[0] * invc;
    double vd = d_stats[1] * invc - md * md;
    float mean = (float)md;
    float inv = rsqrtf((float)vd + 1e-5f);
    float4 hv = ((const float4*)h)[(size_t)gw * 32 + lane];
    float4 hn;
    hn.x = (hv.x - mean) * inv; hn.y = (hv.y - mean) * inv;
    hn.z = (hv.z - mean) * inv; hn.w = (hv.w - mean) * inv;
    float4 a = ((const float4*)p0)[lane];
    float4 b = ((const float4*)(p0 + HH))[lane];
    float d0 = hn.x * a.x + hn.y * a.y + hn.z * a.z + hn.w * a.w;
    float d1 = hn.x * b.x + hn.y * b.y + hn.z * b.z + hn.w * b.w;
#pragma unroll
    for (int o = 16; o; o >>= 1) {
        d0 += __shfl_xor_sync(0xffffffffu, d0, o);
        d1 += __shfl_xor_sync(0xffffffffu, d1, o);
    }
    float g1 = 1.f / (1.f + expf(-d0));
    float g2 = tanhf(d1);
    float gate = pa[0] * g1 + pa[1] * g2 + pa[2];
    float kv = gate > 0.01f ? 1.f : 0.f;
    float sc = gate * kv;
    hn.x *= sc; hn.y *= sc; hn.z *= sc; hn.w *= sc;
    ((float4*)h)[(size_t)gw * 32 + lane] = hn;
    size_t idx = (size_t)gw * HH + lane * 4;
    split_store4(d_hhi, d_hlo, idx, hn);
    if (lane == 0) d_kc[gw] *= kv;
}

// ---------------- readout ----------------------------------------------------
__global__ void readout_kernel(const float* __restrict__ h, int r) {
    int g = blockIdx.x, k = threadIdx.x;
    int b = d_gs[g], e = d_gs[g + 1];
    float s = 0.f, mx = -INFINITY;
    for (int n = b; n < e; n++) {
        float v = h[(size_t)n * HH + k];
        s += v;
        mx = fmaxf(mx, v);
    }
    float c = (float)(e - b);
    float mean = s / fmaxf(c, 1.f);
    if (e == b) mx = 0.f;
    const float* w = d_roa + r * 3;
    d_reps[((size_t)r * GG + g) * HH + k] = w[0] * mean + w[1] * mx + w[2] * s;
}

// ---------------- final head -------------------------------------------------
__global__ void final_head(const float* __restrict__ Wo, const float* __restrict__ bo,
                           const float* __restrict__ Wc, const float* __restrict__ bc,
                           float* __restrict__ out) {
    __shared__ float zr[HH];
    __shared__ float z2[HH];
    __shared__ float lg[OUTC];
    __shared__ float s_lse;
    int g = blockIdx.x, k = threadIdx.x;
    int idx = g * HH + k;
    float r0 = d_reps[idx];
    float r1 = d_reps[GG * HH + idx];
    float r2 = d_reps[2 * GG * HH + idx];
    float r3 = d_reps[3 * GG * HH + idx];
    float s = r0 + r1 + r2 + r3;
    float mx = fmaxf(fmaxf(r0, r1), fmaxf(r2, r3));
    zr[k] = d_laa[0] * eluf(s) + d_laa[1] * eluf(s * 0.25f) + d_laa[2] * eluf(mx);
    __syncthreads();
    float acc = bo[k];
    for (int k2 = 0; k2 < HH; k2++) acc = fmaf(zr[k2], Wo[k2 * HH + k], acc);
    z2[k] = eluf(acc);
    __syncthreads();
    if (k < OUTC) {
        float accl = bc[k];
        for (int k2 = 0; k2 < HH; k2++) accl = fmaf(z2[k2], Wc[k2 * OUTC + k], accl);
        lg[k] = accl;
    }
    __syncthreads();
    if (k == 0) {
        float m = lg[0];
        for (int i = 1; i < OUTC; i++) m = fmaxf(m, lg[i]);
        float se = 0.f;
        for (int i = 0; i < OUTC; i++) se += expf(lg[i] - m);
        s_lse = m + logf(se);
    }
    __syncthreads();
    if (k < OUTC) out[g * OUTC + k] = lg[k] - s_lse;
}

// ---------------- launch ------------------------------------------------------
extern "C" void kernel_launch(void* const* d_in, const int* in_sizes, int n_in,
                              void* d_out, int out_size) {
    const float* x         = (const float*)d_in[0];
    const int*   ei        = (const int*)d_in[1];
    const int*   batch     = (const int*)d_in[2];
    const float* lin1_W    = (const float*)d_in[3];
    const float* lin1_b    = (const float*)d_in[4];
    const float* gnn_W     = (const float*)d_in[5];
    const float* pool_p    = (const float*)d_in[6];
    const float* lin_out_W = (const float*)d_in[7];
    const float* lin_out_b = (const float*)d_in[8];
    const float* cls_W     = (const float*)d_in[9];
    const float* cls_b     = (const float*)d_in[10];
    const float* na_log    = (const float*)d_in[11];
    const float* pool_log  = (const float*)d_in[12];
    const float* ro_log    = (const float*)d_in[13];
    const float* la_log    = (const float*)d_in[14];
    float* out = (float*)d_out;

    float *bufA, *bufB, *naa, *pa;
    __nv_bfloat16 *hhi, *hlo, *shi, *slo, *srhi, *srlo, *ghi, *glo;
    __nv_bfloat16 *Bchi, *Bclo, *B1hi, *B1lo;
    cudaGetSymbolAddress((void**)&bufA, d_bufA);
    cudaGetSymbolAddress((void**)&bufB, d_bufB);
    cudaGetSymbolAddress((void**)&naa, d_naa);
    cudaGetSymbolAddress((void**)&pa, d_pa);
    cudaGetSymbolAddress((void**)&hhi, d_hhi);
    cudaGetSymbolAddress((void**)&hlo, d_hlo);
    cudaGetSymbolAddress((void**)&shi, d_shi);
    cudaGetSymbolAddress((void**)&slo, d_slo);
    cudaGetSymbolAddress((void**)&srhi, d_srhi);
    cudaGetSymbolAddress((void**)&srlo, d_srlo);
    cudaGetSymbolAddress((void**)&ghi, d_ghi);
    cudaGetSymbolAddress((void**)&glo, d_glo);
    cudaGetSymbolAddress((void**)&Bchi, d_Bchi);
    cudaGetSymbolAddress((void**)&Bclo, d_Bclo);
    cudaGetSymbolAddress((void**)&B1hi, d_B1hi);
    cudaGetSymbolAddress((void**)&B1lo, d_B1lo);

    cudaFuncSetAttribute(gemm_mma<4, 0>, cudaFuncAttributeMaxDynamicSharedMemorySize, SM_TOTAL);
    cudaFuncSetAttribute(gemm_mma<16, 1>, cudaFuncAttributeMaxDynamicSharedMemorySize, SM_TOTAL);

    const int GB = (NN + 127) / 128;
    const int EB = (EE + 255) / 256;
    const int WB = (NN * 32 + 255) / 256;
    const int NBK = (NN + 255) / 256;

    setup_kernel<<<NBK, 256>>>(batch, na_log, pool_log, ro_log, la_log);
    convert_kernel<<<(NHTOT + HSQ + 255) / 256, 256>>>(x, lin1_W);
    csr_count<<<EB, 256>>>(ei);
    // launch #4 = profiled slot: lin1 GEMM
    gemm_mma<4, 0><<<GB, 256, SM_TOTAL>>>(hhi, hlo, hhi, hlo, hhi, hlo, hhi, hlo,
                                          B1hi, B1lo, bufA, hhi, hlo, lin1_b);
    scan1<<<NBK, 256>>>();
    scan2<<<1, 256>>>();
    scan3<<<NBK, 256>>>();
    csr_fill<<<EB, 256>>>(ei);
    readout_kernel<<<GG, HH>>>(bufA, 0);

    float* hcur = bufA;
    float* hnew = bufB;
    for (int i = 0; i < LL; i++) {
        const float* Wi = gnn_W + (size_t)i * 6 * HSQ;
        combine_deg<<<(4 * HSQ + NN + 255) / 256, 256>>>(Wi, naa + i * 4);
        aggregate_kernel<<<WB, 256>>>(hcur);
        gemm_mma<16, 1><<<GB, 256, SM_TOTAL>>>(hhi, hlo, shi, slo, srhi, srlo, ghi, glo,
                                               Bchi, Bclo, hnew, nullptr, nullptr,
                                               nullptr);
        gate_kernel<<<WB, 256>>>(hnew, pool_p + (size_t)i * 2 * HH, pa + i * 3);
        readout_kernel<<<GG, HH>>>(hnew, i + 1);
        float* t = hcur; hcur = hnew; hnew = t;
    }

    final_head<<<GG, HH>>>(lin_out_W, lin_out_b, cls_W, cls_b, out);
}

// round 9
// speedup vs baseline: 1.0065x; 1.0065x over previous
#include <cuda_runtime.h>
#include <cuda_bf16.h>
#include <math.h>
#include <cstdint>

#define NN 50000
#define EE 800000
#define GG 512
#define HH 128
#define LL 3
#define OUTC 10
#define NHTOT (NN * HH)
#define HSQ (HH * HH)
#define NB ((NN + 255) / 256)
#define KBIG 512
#define NP 50176
#define NPH (NP * HH)   // elements per split plane (6422528)

// ---------------- scratch (device globals) ----------------------------------
__device__ float  d_bufA[NHTOT];
__device__ float  d_bufB[NHTOT];
__device__ float  d_kc[NN];
__device__ float  d_rs[NN];
__device__ float  d_rdeg[NN];
__device__ int    d_rp[NN + 1];
__device__ int    d_cnt[NN];
__device__ int    d_bsum[NB];
__device__ int    d_colsrc[EE];
__device__ float  d_reps[(LL + 1) * GG * HH];
// ONE packed operand buffer: chunk c (0=h,1=s,2=sr,3=g): hi at 2c*NPH, lo at (2c+1)*NPH
__device__ __nv_bfloat16 d_A[8ULL * NPH];
__device__ __nv_bfloat16 d_B[2 * KBIG * HH];   // [n][k] hi block then lo block
__device__ __nv_bfloat16 d_B1[2 * HSQ];        // lin1 W [n][k] hi then lo
__device__ int    d_gs[GG + 1];
__device__ float  d_naa[LL * 4];
__device__ float  d_pa[LL * 3];
__device__ float  d_roa[(LL + 1) * 3];
__device__ float  d_laa[3];
__device__ double d_stats[2];

__device__ __forceinline__ float eluf(float x) { return x > 0.f ? x : expm1f(x); }

__device__ __forceinline__ uint32_t smem_u32(const void* p) {
    uint32_t a;
    asm("{ .reg .u64 t; cvta.to.shared.u64 t, %1; cvt.u32.u64 %0, t; }" : "=r"(a) : "l"(p));
    return a;
}

__device__ __forceinline__ void ldm_x4(uint32_t r[4], uint32_t addr) {
    asm volatile("ldmatrix.sync.aligned.m8n8.x4.shared.b16 {%0,%1,%2,%3}, [%4];"
                 : "=r"(r[0]), "=r"(r[1]), "=r"(r[2]), "=r"(r[3]) : "r"(addr));
}

__device__ __forceinline__ void mma_bf16(float c[4], const uint32_t a[4],
                                         uint32_t b0, uint32_t b1) {
    asm volatile(
        "mma.sync.aligned.m16n8k16.row.col.f32.bf16.bf16.f32 "
        "{%0,%1,%2,%3},{%4,%5,%6,%7},{%8,%9},{%0,%1,%2,%3};"
        : "+f"(c[0]), "+f"(c[1]), "+f"(c[2]), "+f"(c[3])
        : "r"(a[0]), "r"(a[1]), "r"(a[2]), "r"(a[3]), "r"(b0), "r"(b1));
}

#define CP_ASYNC16(dst, src) asm volatile("cp.async.cg.shared.global [%0], [%1], 16;" :: "r"(dst), "l"(src))
#define CP_COMMIT()          asm volatile("cp.async.commit_group;")
#define CP_WAIT(n)           asm volatile("cp.async.wait_group %0;" :: "n"(n))

// 64B-row smem tile (32 bf16/row), XOR swizzle; addr(k0+16) = addr(k0) ^ 32
__device__ __forceinline__ uint32_t swz32(int row, int col) {
    return (uint32_t)(row * 64 + ((((col >> 3) ^ ((row >> 1) & 3))) << 4));
}

__device__ __forceinline__ void split_store4(__nv_bfloat16* hi, __nv_bfloat16* lo,
                                             size_t idx, float4 v) {
    __nv_bfloat162 h0 = __floats2bfloat162_rn(v.x, v.y);
    __nv_bfloat162 h1 = __floats2bfloat162_rn(v.z, v.w);
    float2 f0 = __bfloat1622float2(h0), f1 = __bfloat1622float2(h1);
    *(__nv_bfloat162*)&hi[idx]     = h0;
    *(__nv_bfloat162*)&hi[idx + 2] = h1;
    *(__nv_bfloat162*)&lo[idx]     = __floats2bfloat162_rn(v.x - f0.x, v.y - f0.y);
    *(__nv_bfloat162*)&lo[idx + 2] = __floats2bfloat162_rn(v.z - f1.x, v.w - f1.y);
}

// stage: AHI(8K) ALO(8K) BHI(8K) BLO(8K) = 32KB; 3 stages = 96KB
#define STG_SZ   32768
#define OFF_ALO  8192
#define OFF_BHI  16384
#define OFF_BLO  24576
#define SM_TOTAL 98304

// ---------------- tensor-core GEMM ------------------------------------------
// Packed operands: A chunks at 2c*NPH (hi) / (2c+1)*NPH (lo); B lo at KB*128.
// NSLICES = K/32, chunk = slice>>2.
// MODE 0: bias+elu, writes C + split back into A chunk 0.   MODE 1: elu + LN stats
template <int NSLICES, int MODE>
__global__ void __launch_bounds__(256, 2) gemm_mma(
    const __nv_bfloat16* __restrict__ A, const __nv_bfloat16* __restrict__ B,
    float* __restrict__ C, __nv_bfloat16* __restrict__ Csp,
    const float* __restrict__ bias) {
    extern __shared__ char smem[];
    uint32_t sb = smem_u32(smem);
    const int tid = threadIdx.x;
    const int wid = tid >> 5, lane = tid & 31;
    const int warp_m = wid & 1, warp_n = wid >> 1;
    const int bm = blockIdx.x * 128;
    const int KB = NSLICES * 32;
    const int BLO = KB * 128;  // B lo block offset (elements)

    const int lrow = tid >> 1;
    const int lcol = (tid & 1) * 16;
    const uint32_t arow = (uint32_t)(bm + lrow) * HH + lcol;
    const uint32_t brow = (uint32_t)lrow * KB + lcol;

    uint32_t st_d[2];
    st_d[0] = swz32(lrow, lcol);
    st_d[1] = swz32(lrow, lcol + 8);
    const int lr = lane & 15, lg2 = (lane >> 4) * 8;
    const int m_base = warp_m * 64;
    const int n_base = warp_n * 32;
    uint32_t aoff[4], boff[2];
#pragma unroll
    for (int mt = 0; mt < 4; mt++) aoff[mt] = sb + swz32(m_base + mt * 16 + lr, lg2);
#pragma unroll
    for (int np = 0; np < 2; np++) boff[np] = sb + OFF_BHI + swz32(n_base + np * 16 + lr, lg2);

    float acc[4][4][4];
#pragma unroll
    for (int i = 0; i < 4; i++)
#pragma unroll
        for (int j = 0; j < 4; j++)
#pragma unroll
            for (int q = 0; q < 4; q++) acc[i][j][q] = 0.f;

#pragma unroll
    for (int pf = 0; pf < 2; pf++) {
        const __nv_bfloat16* ap = A + (size_t)(pf >> 2) * (2 * (size_t)NPH) + arow + (pf & 3) * 32;
        const __nv_bfloat16* bp = B + brow + pf * 32;
        uint32_t base = sb + pf * STG_SZ;
#pragma unroll
        for (int j = 0; j < 2; j++) {
            uint32_t d = base + st_d[j];
            CP_ASYNC16(d,           ap + j * 8);
            CP_ASYNC16(d + OFF_ALO, ap + NPH + j * 8);
            CP_ASYNC16(d + OFF_BHI, bp + j * 8);
            CP_ASYNC16(d + OFF_BLO, bp + BLO + j * 8);
        }
        CP_COMMIT();
    }

#pragma unroll
    for (int s = 0; s < NSLICES; s++) {
        if (s + 2 < NSLICES) {
            const int sn = s + 2;
            const __nv_bfloat16* ap = A + (size_t)(sn >> 2) * (2 * (size_t)NPH) + arow + (sn & 3) * 32;
            const __nv_bfloat16* bp = B + brow + sn * 32;
            uint32_t base = sb + (sn % 3) * STG_SZ;
#pragma unroll
            for (int j = 0; j < 2; j++) {
                uint32_t d = base + st_d[j];
                CP_ASYNC16(d,           ap + j * 8);
                CP_ASYNC16(d + OFF_ALO, ap + NPH + j * 8);
                CP_ASYNC16(d + OFF_BHI, bp + j * 8);
                CP_ASYNC16(d + OFF_BLO, bp + BLO + j * 8);
            }
            CP_COMMIT();
            CP_WAIT(2);
        } else if (s + 2 == NSLICES) {
            CP_WAIT(1);
        } else {
            CP_WAIT(0);
        }
        __syncthreads();
        const uint32_t sbase = (uint32_t)((s % 3) * STG_SZ);
#pragma unroll
        for (int ks = 0; ks < 2; ks++) {
            const uint32_t kx = ks * 32;
            uint32_t bhm[2][4], blm[2][4];
#pragma unroll
            for (int np = 0; np < 2; np++) {
                uint32_t ad = sbase + (boff[np] ^ kx);
                ldm_x4(bhm[np], ad);
                ldm_x4(blm[np], ad + (OFF_BLO - OFF_BHI));
            }
#pragma unroll
            for (int mt = 0; mt < 4; mt++) {
                uint32_t ad = sbase + (aoff[mt] ^ kx);
                uint32_t ah[4], al[4];
                ldm_x4(ah, ad);
                ldm_x4(al, ad + OFF_ALO);
#pragma unroll
                for (int nt = 0; nt < 4; nt++) {
                    int np = nt >> 1, sel = nt & 1;
                    uint32_t b0h = sel ? bhm[np][1] : bhm[np][0];
                    uint32_t b1h = sel ? bhm[np][3] : bhm[np][2];
                    uint32_t b0l = sel ? blm[np][1] : blm[np][0];
                    uint32_t b1l = sel ? blm[np][3] : blm[np][2];
                    mma_bf16(acc[mt][nt], ah, b0h, b1h);
                    mma_bf16(acc[mt][nt], al, b0h, b1h);
                    mma_bf16(acc[mt][nt], ah, b0l, b1l);
                }
            }
        }
        __syncthreads();
    }

    // ---- epilogue
    float lsum = 0.f, lsq = 0.f;
    int rq = lane >> 2, cq = (lane & 3) * 2;
#pragma unroll
    for (int mt = 0; mt < 4; mt++) {
#pragma unroll
        for (int half = 0; half < 2; half++) {
            int gm = bm + m_base + mt * 16 + rq + half * 8;
            if (gm >= NN) continue;
#pragma unroll
            for (int nt = 0; nt < 4; nt++) {
                int col = n_base + nt * 8 + cq;
                float v0 = acc[mt][nt][half * 2];
                float v1 = acc[mt][nt][half * 2 + 1];
                if (MODE == 0) {
                    v0 = eluf(v0 + bias[col]);
                    v1 = eluf(v1 + bias[col + 1]);
                    __nv_bfloat162 h = __floats2bfloat162_rn(v0, v1);
                    float2 hf = __bfloat1622float2(h);
                    size_t ci = (size_t)gm * HH + col;
                    *(__nv_bfloat162*)&Csp[ci] = h;
                    *(__nv_bfloat162*)&Csp[NPH + ci] =
                        __floats2bfloat162_rn(v0 - hf.x, v1 - hf.y);
                } else {
                    v0 = eluf(v0); v1 = eluf(v1);
                    lsum += v0 + v1;
                    lsq = fmaf(v0, v0, lsq); lsq = fmaf(v1, v1, lsq);
                }
                *(float2*)&C[(size_t)gm * HH + col] = make_float2(v0, v1);
            }
        }
    }
    if (MODE == 1) {
        double ds = (double)lsum, dq = (double)lsq;
#pragma unroll
        for (int o = 16; o; o >>= 1) {
            ds += __shfl_down_sync(0xffffffffu, ds, o);
            dq += __shfl_down_sync(0xffffffffu, dq, o);
        }
        __shared__ double ssum[8], ssq[8];
        if (lane == 0) { ssum[wid] = ds; ssq[wid] = dq; }
        __syncthreads();
        if (tid == 0) {
            double a = 0.0, b = 0.0;
#pragma unroll
            for (int i = 0; i < 8; i++) { a += ssum[i]; b += ssq[i]; }
            atomicAdd(&d_stats[0], a);
            atomicAdd(&d_stats[1], b);
        }
    }
}

// ---------------- setup ------------------------------------------------------
__device__ void softmax_n(const float* in, float* out, int n) {
    float m = in[0];
    for (int i = 1; i < n; i++) m = fmaxf(m, in[i]);
    float s = 0.f;
    for (int i = 0; i < n; i++) { out[i] = expf(in[i] - m); s += out[i]; }
    float inv = 1.f / s;
    for (int i = 0; i < n; i++) out[i] *= inv;
}

__global__ void setup_kernel(const int* __restrict__ batch,
                             const float* __restrict__ na, const float* __restrict__ pl,
                             const float* __restrict__ ro, const float* __restrict__ la) {
    int i = blockIdx.x * blockDim.x + threadIdx.x;
    if (i <= GG) {
        int lo = 0, hi = NN;
        while (lo < hi) { int mid = (lo + hi) >> 1; if (batch[mid] < i) lo = mid + 1; else hi = mid; }
        d_gs[i] = lo;
    }
    if (i < NN) { d_kc[i] = 1.f; d_cnt[i] = 0; }
    if (i == 0) {
        for (int l = 0; l < LL; l++) softmax_n(na + l * 4, d_naa + l * 4, 4);
        for (int l = 0; l < LL; l++) softmax_n(pl + l * 3, d_pa + l * 3, 3);
        for (int l = 0; l < LL + 1; l++) softmax_n(ro + l * 3, d_roa + l * 3, 3);
        softmax_n(la, d_laa, 3);
    }
}

__global__ void convert_kernel(const float* __restrict__ x, const float* __restrict__ W) {
    int idx = blockIdx.x * blockDim.x + threadIdx.x;
    if (idx < NHTOT) {
        float v = x[idx];
        __nv_bfloat16 h = __float2bfloat16(v);
        d_A[idx] = h;
        d_A[NPH + idx] = __float2bfloat16(v - __bfloat162float(h));
    } else if (idx < NHTOT + HSQ) {
        int i = idx - NHTOT;
        int k = i >> 7, n = i & 127;
        float v = W[k * HH + n];
        __nv_bfloat16 h = __float2bfloat16(v);
        d_B1[n * HH + k] = h;
        d_B1[HSQ + n * HH + k] = __float2bfloat16(v - __bfloat162float(h));
    }
}

__global__ void csr_count(const int* __restrict__ ei) {
    int e = blockIdx.x * blockDim.x + threadIdx.x;
    if (e >= EE) return;
    atomicAdd(&d_cnt[ei[EE + e]], 1);
}

__global__ void scan1() {
    __shared__ int sh[256];
    int i = blockIdx.x * 256 + threadIdx.x;
    int v = (i < NN) ? d_cnt[i] : 0;
    sh[threadIdx.x] = v;
    __syncthreads();
#pragma unroll
    for (int d = 1; d < 256; d <<= 1) {
        int t = (threadIdx.x >= d) ? sh[threadIdx.x - d] : 0;
        __syncthreads();
        sh[threadIdx.x] += t;
        __syncthreads();
    }
    if (i < NN) d_rp[i + 1] = sh[threadIdx.x];
    if (threadIdx.x == 255) d_bsum[blockIdx.x] = sh[255];
}

__global__ void scan2() {
    __shared__ int sh[256];
    int t = threadIdx.x;
    int v = (t < NB) ? d_bsum[t] : 0;
    sh[t] = v;
    __syncthreads();
#pragma unroll
    for (int d = 1; d < 256; d <<= 1) {
        int tv = (t >= d) ? sh[t - d] : 0;
        __syncthreads();
        sh[t] += tv;
        __syncthreads();
    }
    if (t < NB) d_bsum[t] = sh[t] - v;
}

__global__ void scan3() {
    int i = blockIdx.x * 256 + threadIdx.x;
    if (i < NN) d_rp[i + 1] += d_bsum[blockIdx.x];
    if (i == 0) d_rp[0] = 0;
}

__global__ void csr_fill(const int* __restrict__ ei) {
    int e = blockIdx.x * blockDim.x + threadIdx.x;
    if (e >= EE) return;
    int d = ei[EE + e];
    int old = atomicSub(&d_cnt[d], 1);
    d_colsrc[d_rp[d] + old - 1] = ei[e];
}

// combine_W + deg + stats zero
__global__ void combine_deg(const float* __restrict__ W, const float* __restrict__ na) {
    int idx = blockIdx.x * blockDim.x + threadIdx.x;
    if (idx == 0) { d_stats[0] = 0.0; d_stats[1] = 0.0; }
    if (idx < 4 * HSQ) {
        int k = idx >> 7, n = idx & 127;
        int p = k >> 7, kk = k & 127;
        int widx = kk * HH + n;
        float a0 = na[0], a1 = na[1], a2 = na[2], a3 = na[3];
        float v;
        if (p == 0)      v = a1 * W[2 * HSQ + widx] + a2 * W[3 * HSQ + widx] + a3 * W[4 * HSQ + widx];
        else if (p == 1) v = a2 * W[3 * HSQ + widx] + a3 * W[5 * HSQ + widx];  // x s_agg
        else if (p == 2) v = a1 * W[1 * HSQ + widx];                            // x s_agg*rdeg
        else             v = a0 * W[widx];                                      // x g_agg
        __nv_bfloat16 h = __float2bfloat16(v);
        d_B[(size_t)n * KBIG + k] = h;
        d_B[KBIG * HH + (size_t)n * KBIG + k] = __float2bfloat16(v - __bfloat162float(h));
    } else {
        int n = idx - 4 * HSQ;
        if (n < NN) {
            float kcn = d_kc[n];
            float s = kcn;
            int b = d_rp[n], e = d_rp[n + 1];
            for (int p = b; p < e; p++) s += d_kc[d_colsrc[p]];
            float dg = fmaxf(kcn * s, 1e-6f);
            d_rdeg[n] = 1.f / dg;
            d_rs[n] = rsqrtf(dg);
        }
    }
}

// ---------------- gather aggregation ----------------------------------------
__global__ void aggregate_kernel(const float* __restrict__ h) {
    int gw = (blockIdx.x * blockDim.x + threadIdx.x) >> 5;
    int lane = threadIdx.x & 31;
    if (gw >= NN) return;
    float kcd = d_kc[gw];
    float rsd = d_rs[gw];
    float rdg = d_rdeg[gw];
    const float4* h4 = (const float4*)h;
    float4 hv = h4[(size_t)gw * 32 + lane];
    float wg = kcd * rsd;
    float4 as = {hv.x * kcd, hv.y * kcd, hv.z * kcd, hv.w * kcd};
    float4 ag = {hv.x * wg, hv.y * wg, hv.z * wg, hv.w * wg};
    int beg = d_rp[gw], end = d_rp[gw + 1];
    for (int p = beg; p < end; p++) {
        int s = d_colsrc[p];
        float w1 = d_kc[s];
        if (w1 != 0.f) {
            float rv = d_rs[s];
            float4 hs = h4[(size_t)s * 32 + lane];
            as.x += hs.x; as.y += hs.y; as.z += hs.z; as.w += hs.w;
            ag.x = fmaf(hs.x, rv, ag.x); ag.y = fmaf(hs.y, rv, ag.y);
            ag.z = fmaf(hs.z, rv, ag.z); ag.w = fmaf(hs.w, rv, ag.w);
        }
    }
    float fg = kcd * rsd;
    as.x *= kcd; as.y *= kcd; as.z *= kcd; as.w *= kcd;
    ag.x *= fg;  ag.y *= fg;  ag.z *= fg;  ag.w *= fg;
    float4 asr = {as.x * rdg, as.y * rdg, as.z * rdg, as.w * rdg};
    size_t idx = (size_t)gw * HH + lane * 4;
    split_store4(d_A + 2ULL * NPH, d_A + 3ULL * NPH, idx, as);
    split_store4(d_A + 4ULL * NPH, d_A + 5ULL * NPH, idx, asr);
    split_store4(d_A + 6ULL * NPH, d_A + 7ULL * NPH, idx, ag);
}

// ---------------- layernorm + gate + pool -----------------------------------
__global__ void gate_kernel(float* __restrict__ h, const float* __restrict__ p0,
                            const float* __restrict__ pa) {
    int gw = (blockIdx.x * blockDim.x + threadIdx.x) >> 5;
    int lane = threadIdx.x & 31;
    if (gw >= NN) return;
    const double invc = 1.0 / ((double)NN * (double)HH);
    double md = d_stats[0] * invc;
    double vd = d_stats[1] * invc - md * md;
    float mean = (float)md;
    float inv = rsqrtf((float)vd + 1e-5f);
    float4 hv = ((const float4*)h)[(size_t)gw * 32 + lane];
    float4 hn;
    hn.x = (hv.x - mean) * inv; hn.y = (hv.y - mean) * inv;
    hn.z = (hv.z - mean) * inv; hn.w = (hv.w - mean) * inv;
    float4 a = ((const float4*)p0)[lane];
    float4 b = ((const float4*)(p0 + HH))[lane];
    float d0 = hn.x * a.x + hn.y * a.y + hn.z * a.z + hn.w * a.w;
    float d1 = hn.x * b.x + hn.y * b.y + hn.z * b.z + hn.w * b.w;
#pragma unroll
    for (int o = 16; o; o >>= 1) {
        d0 += __shfl_xor_sync(0xffffffffu, d0, o);
        d1 += __shfl_xor_sync(0xffffffffu, d1, o);
    }
    float g1 = 1.f / (1.f + expf(-d0));
    float g2 = tanhf(d1);
    float gate = pa[0] * g1 + pa[1] * g2 + pa[2];
    float kv = gate > 0.01f ? 1.f : 0.f;
    float sc = gate * kv;
    hn.x *= sc; hn.y *= sc; hn.z *= sc; hn.w *= sc;
    ((float4*)h)[(size_t)gw * 32 + lane] = hn;
    size_t idx = (size_t)gw * HH + lane * 4;
    split_store4(d_A, d_A + NPH, idx, hn);
    if (lane == 0) d_kc[gw] *= kv;
}

// ---------------- readout ----------------------------------------------------
__global__ void readout_kernel(const float* __restrict__ h, int r) {
    int g = blockIdx.x, k = threadIdx.x;
    int b = d_gs[g], e = d_gs[g + 1];
    float s = 0.f, mx = -INFINITY;
    for (int n = b; n < e; n++) {
        float v = h[(size_t)n * HH + k];
        s += v;
        mx = fmaxf(mx, v);
    }
    float c = (float)(e - b);
    float mean = s / fmaxf(c, 1.f);
    if (e == b) mx = 0.f;
    const float* w = d_roa + r * 3;
    d_reps[((size_t)r * GG + g) * HH + k] = w[0] * mean + w[1] * mx + w[2] * s;
}

// ---------------- final head -------------------------------------------------
__global__ void final_head(const float* __restrict__ Wo, const float* __restrict__ bo,
                           const float* __restrict__ Wc, const float* __restrict__ bc,
                           float* __restrict__ out) {
    __shared__ float zr[HH];
    __shared__ float z2[HH];
    __shared__ float lg[OUTC];
    __shared__ float s_lse;
    int g = blockIdx.x, k = threadIdx.x;
    int idx = g * HH + k;
    float r0 = d_reps[idx];
    float r1 = d_reps[GG * HH + idx];
    float r2 = d_reps[2 * GG * HH + idx];
    float r3 = d_reps[3 * GG * HH + idx];
    float s = r0 + r1 + r2 + r3;
    float mx = fmaxf(fmaxf(r0, r1), fmaxf(r2, r3));
    zr[k] = d_laa[0] * eluf(s) + d_laa[1] * eluf(s * 0.25f) + d_laa[2] * eluf(mx);
    __syncthreads();
    float acc = bo[k];
    for (int k2 = 0; k2 < HH; k2++) acc = fmaf(zr[k2], Wo[k2 * HH + k], acc);
    z2[k] = eluf(acc);
    __syncthreads();
    if (k < OUTC) {
        float accl = bc[k];
        for (int k2 = 0; k2 < HH; k2++) accl = fmaf(z2[k2], Wc[k2 * OUTC + k], accl);
        lg[k] = accl;
    }
    __syncthreads();
    if (k == 0) {
        float m = lg[0];
        for (int i = 1; i < OUTC; i++) m = fmaxf(m, lg[i]);
        float se = 0.f;
        for (int i = 0; i < OUTC; i++) se += expf(lg[i] - m);
        s_lse = m + logf(se);
    }
    __syncthreads();
    if (k < OUTC) out[g * OUTC + k] = lg[k] - s_lse;
}

// ---------------- launch ------------------------------------------------------
extern "C" void kernel_launch(void* const* d_in, const int* in_sizes, int n_in,
                              void* d_out, int out_size) {
    const float* x         = (const float*)d_in[0];
    const int*   ei        = (const int*)d_in[1];
    const int*   batch     = (const int*)d_in[2];
    const float* lin1_W    = (const float*)d_in[3];
    const float* lin1_b    = (const float*)d_in[4];
    const float* gnn_W     = (const float*)d_in[5];
    const float* pool_p    = (const float*)d_in[6];
    const float* lin_out_W = (const float*)d_in[7];
    const float* lin_out_b = (const float*)d_in[8];
    const float* cls_W     = (const float*)d_in[9];
    const float* cls_b     = (const float*)d_in[10];
    const float* na_log    = (const float*)d_in[11];
    const float* pool_log  = (const float*)d_in[12];
    const float* ro_log    = (const float*)d_in[13];
    const float* la_log    = (const float*)d_in[14];
    float* out = (float*)d_out;

    float *bufA, *bufB, *naa, *pa;
    __nv_bfloat16 *Ab, *Bb, *B1b;
    cudaGetSymbolAddress((void**)&bufA, d_bufA);
    cudaGetSymbolAddress((void**)&bufB, d_bufB);
    cudaGetSymbolAddress((void**)&naa, d_naa);
    cudaGetSymbolAddress((void**)&pa, d_pa);
    cudaGetSymbolAddress((void**)&Ab, d_A);
    cudaGetSymbolAddress((void**)&Bb, d_B);
    cudaGetSymbolAddress((void**)&B1b, d_B1);

    cudaFuncSetAttribute(gemm_mma<4, 0>, cudaFuncAttributeMaxDynamicSharedMemorySize, SM_TOTAL);
    cudaFuncSetAttribute(gemm_mma<16, 1>, cudaFuncAttributeMaxDynamicSharedMemorySize, SM_TOTAL);

    const int GB = (NN + 127) / 128;
    const int EB = (EE + 255) / 256;
    const int WB = (NN * 32 + 255) / 256;
    const int NBK = (NN + 255) / 256;

    setup_kernel<<<NBK, 256>>>(batch, na_log, pool_log, ro_log, la_log);
    convert_kernel<<<(NHTOT + HSQ + 255) / 256, 256>>>(x, lin1_W);
    csr_count<<<EB, 256>>>(ei);
    // launch #4 = profiled slot: lin1 GEMM (reads x-split chunk0, writes h-split chunk0)
    gemm_mma<4, 0><<<GB, 256, SM_TOTAL>>>(Ab, B1b, bufA, Ab, lin1_b);
    scan1<<<NBK, 256>>>();
    scan2<<<1, 256>>>();
    scan3<<<NBK, 256>>>();
    csr_fill<<<EB, 256>>>(ei);
    readout_kernel<<<GG, HH>>>(bufA, 0);

    float* hcur = bufA;
    float* hnew = bufB;
    for (int i = 0; i < LL; i++) {
        const float* Wi = gnn_W + (size_t)i * 6 * HSQ;
        combine_deg<<<(4 * HSQ + NN + 255) / 256, 256>>>(Wi, naa + i * 4);
        aggregate_kernel<<<WB, 256>>>(hcur);
        gemm_mma<16, 1><<<GB, 256, SM_TOTAL>>>(Ab, Bb, hnew, nullptr, nullptr);
        gate_kernel<<<WB, 256>>>(hnew, pool_p + (size_t)i * 2 * HH, pa + i * 3);
        readout_kernel<<<GG, HH>>>(hnew, i + 1);
        float* t = hcur; hcur = hnew; hnew = t;
    }

    final_head<<<GG, HH>>>(lin_out_W, lin_out_b, cls_W, cls_b, out);
}

// round 10
// speedup vs baseline: 1.0603x; 1.0534x over previous
#include <cuda_runtime.h>
#include <cuda_bf16.h>
#include <math.h>
#include <cstdint>

#define NN 50000
#define EE 800000
#define GG 512
#define HH 128
#define LL 3
#define OUTC 10
#define NHTOT (NN * HH)
#define HSQ (HH * HH)
#define NB ((NN + 255) / 256)
#define KBIG 512
#define NP 50176
#define NPH (NP * HH)

// ---------------- scratch (device globals) ----------------------------------
__device__ float  d_bufA[NHTOT];
__device__ float  d_bufB[NHTOT];
__device__ float  d_kc[NN];
__device__ float  d_rs[NN];
__device__ float  d_rdeg[NN];
__device__ int    d_rp[NN + 1];
__device__ int    d_cnt[NN];
__device__ int    d_bsum[NB];
__device__ int    d_colsrc[EE];
__device__ float  d_reps[(LL + 1) * GG * HH];
// GEMM input planes: chunk c (0=h,1=s,2=sr,3=g): hi at 2c*NPH, lo at (2c+1)*NPH
__device__ __nv_bfloat16 d_A[8ULL * NPH];
// GEMM output / x-input planes: hi at 0, lo at NPH
__device__ __nv_bfloat16 d_Hn[2ULL * NPH];
__device__ __nv_bfloat16 d_B[2 * KBIG * HH];   // [n][k] hi block then lo block
__device__ __nv_bfloat16 d_B1[2 * HSQ];        // lin1 W [n][k] hi then lo
__device__ int    d_gs[GG + 1];
__device__ float  d_naa[LL * 4];
__device__ float  d_pa[LL * 3];
__device__ float  d_roa[(LL + 1) * 3];
__device__ float  d_laa[3];
__device__ double d_stats[2];

__device__ __forceinline__ float eluf(float x) { return x > 0.f ? x : expm1f(x); }

__device__ __forceinline__ uint32_t smem_u32(const void* p) {
    uint32_t a;
    asm("{ .reg .u64 t; cvta.to.shared.u64 t, %1; cvt.u32.u64 %0, t; }" : "=r"(a) : "l"(p));
    return a;
}

__device__ __forceinline__ void ldm_x4(uint32_t r[4], uint32_t addr) {
    asm volatile("ldmatrix.sync.aligned.m8n8.x4.shared.b16 {%0,%1,%2,%3}, [%4];"
                 : "=r"(r[0]), "=r"(r[1]), "=r"(r[2]), "=r"(r[3]) : "r"(addr));
}

__device__ __forceinline__ void mma_bf16(float c[4], const uint32_t a[4],
                                         uint32_t b0, uint32_t b1) {
    asm volatile(
        "mma.sync.aligned.m16n8k16.row.col.f32.bf16.bf16.f32 "
        "{%0,%1,%2,%3},{%4,%5,%6,%7},{%8,%9},{%0,%1,%2,%3};"
        : "+f"(c[0]), "+f"(c[1]), "+f"(c[2]), "+f"(c[3])
        : "r"(a[0]), "r"(a[1]), "r"(a[2]), "r"(a[3]), "r"(b0), "r"(b1));
}

#define CP_ASYNC16(dst, src) asm volatile("cp.async.cg.shared.global [%0], [%1], 16;" :: "r"(dst), "l"(src))
#define CP_COMMIT()          asm volatile("cp.async.commit_group;")
#define CP_WAIT(n)           asm volatile("cp.async.wait_group %0;" :: "n"(n))

// 64B-row smem tile (32 bf16/row), XOR swizzle; addr(k0+16) = addr(k0) ^ 32
__device__ __forceinline__ uint32_t swz32(int row, int col) {
    return (uint32_t)(row * 64 + ((((col >> 3) ^ ((row >> 1) & 3))) << 4));
}

__device__ __forceinline__ void split_store4(__nv_bfloat16* hi, __nv_bfloat16* lo,
                                             size_t idx, float4 v) {
    __nv_bfloat162 h0 = __floats2bfloat162_rn(v.x, v.y);
    __nv_bfloat162 h1 = __floats2bfloat162_rn(v.z, v.w);
    float2 f0 = __bfloat1622float2(h0), f1 = __bfloat1622float2(h1);
    *(__nv_bfloat162*)&hi[idx]     = h0;
    *(__nv_bfloat162*)&hi[idx + 2] = h1;
    *(__nv_bfloat162*)&lo[idx]     = __floats2bfloat162_rn(v.x - f0.x, v.y - f0.y);
    *(__nv_bfloat162*)&lo[idx + 2] = __floats2bfloat162_rn(v.z - f1.x, v.w - f1.y);
}

// stage: AHI(8K) ALO(8K) BHI(4K) BLO(4K) = 24KB; 3 stages = 72KB
#define STG_SZ   24576
#define OFF_ALO  8192
#define OFF_BHI  16384
#define OFF_BLO  20480
#define SM_TOTAL 73728

// ---------------- tensor-core GEMM ------------------------------------------
// CTA tile 128(m) x 64(n); warp grid 4m x 2n; warp tile 32x32 (acc = 32 regs).
// A planes: chunk c hi at 2c*NPH, lo at (2c+1)*NPH. B lo plane at KB*128.
// MODE 0: bias+elu, writes fp32 C + split Csp.   MODE 1: elu + LN stats, split Csp only.
template <int NSLICES, int MODE>
__global__ void __launch_bounds__(256, 2) gemm_mma(
    const __nv_bfloat16* __restrict__ A, const __nv_bfloat16* __restrict__ B,
    float* __restrict__ C, __nv_bfloat16* __restrict__ Csp,
    const float* __restrict__ bias) {
    extern __shared__ char smem[];
    uint32_t sb = smem_u32(smem);
    const int tid = threadIdx.x;
    const int wid = tid >> 5, lane = tid & 31;
    const int warp_m = wid & 3, warp_n = wid >> 2;   // 4m x 2n
    const int bm = (blockIdx.x >> 1) * 128;
    const int bn = (blockIdx.x & 1) * 64;
    const int KB = NSLICES * 32;
    const int BLO = KB * 128;

    // --- loader mapping
    const int lrow = tid >> 1;                 // A row 0..127
    const int lc = (tid & 1) * 8;              // A col 0 / 8 (plus +16 second chunk)
    const int brr = tid >> 2;                  // B row 0..63
    const int bcc = (tid & 3) * 8;             // B col chunk
    const uint32_t sA0 = swz32(lrow, lc);
    const uint32_t sA1 = swz32(lrow, lc + 16);
    const uint32_t sB  = OFF_BHI + swz32(brr, bcc);
    const __nv_bfloat16* Abase = A + (size_t)(bm + lrow) * HH + lc;
    const __nv_bfloat16* Bbase = B + (size_t)(bn + brr) * KB + bcc;

    // --- compute mapping
    const int lr = lane & 15, lg2 = (lane >> 4) * 8;
    const int m_base = warp_m * 32;
    const int n_base = warp_n * 32;
    uint32_t aoff[2], boff[2];
#pragma unroll
    for (int mt = 0; mt < 2; mt++) aoff[mt] = swz32(m_base + mt * 16 + lr, lg2);
#pragma unroll
    for (int np = 0; np < 2; np++) boff[np] = OFF_BHI + swz32(n_base + np * 16 + lr, lg2);

    float acc[2][4][4];
#pragma unroll
    for (int i = 0; i < 2; i++)
#pragma unroll
        for (int j = 0; j < 4; j++)
#pragma unroll
            for (int q = 0; q < 4; q++) acc[i][j][q] = 0.f;

    // prologue: slices 0,1
#pragma unroll
    for (int pf = 0; pf < 2; pf++) {
        const __nv_bfloat16* ap = Abase + (size_t)(pf >> 2) * (2 * (size_t)NPH) + (pf & 3) * 32;
        const __nv_bfloat16* bp = Bbase + pf * 32;
        uint32_t base = sb + pf * STG_SZ;
        CP_ASYNC16(base + sA0, ap);
        CP_ASYNC16(base + sA1, ap + 16);
        CP_ASYNC16(base + sA0 + OFF_ALO, ap + NPH);
        CP_ASYNC16(base + sA1 + OFF_ALO, ap + NPH + 16);
        CP_ASYNC16(base + sB, bp);
        CP_ASYNC16(base + sB + (OFF_BLO - OFF_BHI), bp + BLO);
        CP_COMMIT();
    }

#pragma unroll
    for (int s = 0; s < NSLICES; s++) {
        if (s + 1 < NSLICES) { CP_WAIT(1); } else { CP_WAIT(0); }
        __syncthreads();
        if (s + 2 < NSLICES) {
            const int sn = s + 2;
            const __nv_bfloat16* ap = Abase + (size_t)(sn >> 2) * (2 * (size_t)NPH) + (sn & 3) * 32;
            const __nv_bfloat16* bp = Bbase + sn * 32;
            uint32_t base = sb + (sn % 3) * STG_SZ;
            CP_ASYNC16(base + sA0, ap);
            CP_ASYNC16(base + sA1, ap + 16);
            CP_ASYNC16(base + sA0 + OFF_ALO, ap + NPH);
            CP_ASYNC16(base + sA1 + OFF_ALO, ap + NPH + 16);
            CP_ASYNC16(base + sB, bp);
            CP_ASYNC16(base + sB + (OFF_BLO - OFF_BHI), bp + BLO);
            CP_COMMIT();
        }
        const uint32_t sbase = sb + (uint32_t)((s % 3) * STG_SZ);
#pragma unroll
        for (int ks = 0; ks < 2; ks++) {
            const uint32_t kx = ks * 32;
            uint32_t bhm[2][4], blm[2][4];
#pragma unroll
            for (int np = 0; np < 2; np++) {
                uint32_t ad = sbase + (boff[np] ^ kx);
                ldm_x4(bhm[np], ad);
                ldm_x4(blm[np], ad + (OFF_BLO - OFF_BHI));
            }
#pragma unroll
            for (int mt = 0; mt < 2; mt++) {
                uint32_t ad = sbase + (aoff[mt] ^ kx);
                uint32_t ah[4], al[4];
                ldm_x4(ah, ad);
                ldm_x4(al, ad + OFF_ALO);
#pragma unroll
                for (int nt = 0; nt < 4; nt++) {
                    int np = nt >> 1, sel = nt & 1;
                    uint32_t b0h = sel ? bhm[np][1] : bhm[np][0];
                    uint32_t b1h = sel ? bhm[np][3] : bhm[np][2];
                    uint32_t b0l = sel ? blm[np][1] : blm[np][0];
                    uint32_t b1l = sel ? blm[np][3] : blm[np][2];
                    mma_bf16(acc[mt][nt], ah, b0h, b1h);
                    mma_bf16(acc[mt][nt], al, b0h, b1h);
                    mma_bf16(acc[mt][nt], ah, b0l, b1l);
                }
            }
        }
    }
    __syncthreads();

    // ---- epilogue
    float lsum = 0.f, lsq = 0.f;
    int rq = lane >> 2, cq = (lane & 3) * 2;
#pragma unroll
    for (int mt = 0; mt < 2; mt++) {
#pragma unroll
        for (int half = 0; half < 2; half++) {
            int gm = bm + m_base + mt * 16 + rq + half * 8;
            if (gm >= NN) continue;
#pragma unroll
            for (int nt = 0; nt < 4; nt++) {
                int col = bn + n_base + nt * 8 + cq;
                float v0 = acc[mt][nt][half * 2];
                float v1 = acc[mt][nt][half * 2 + 1];
                if (MODE == 0) {
                    v0 = eluf(v0 + bias[col]);
                    v1 = eluf(v1 + bias[col + 1]);
                    *(float2*)&C[(size_t)gm * HH + col] = make_float2(v0, v1);
                } else {
                    v0 = eluf(v0); v1 = eluf(v1);
                    lsum += v0 + v1;
                    lsq = fmaf(v0, v0, lsq); lsq = fmaf(v1, v1, lsq);
                }
                __nv_bfloat162 h = __floats2bfloat162_rn(v0, v1);
                float2 hf = __bfloat1622float2(h);
                size_t ci = (size_t)gm * HH + col;
                *(__nv_bfloat162*)&Csp[ci] = h;
                *(__nv_bfloat162*)&Csp[NPH + ci] =
                    __floats2bfloat162_rn(v0 - hf.x, v1 - hf.y);
            }
        }
    }
    if (MODE == 1) {
        double ds = (double)lsum, dq = (double)lsq;
#pragma unroll
        for (int o = 16; o; o >>= 1) {
            ds += __shfl_down_sync(0xffffffffu, ds, o);
            dq += __shfl_down_sync(0xffffffffu, dq, o);
        }
        __shared__ double ssum[8], ssq[8];
        if (lane == 0) { ssum[wid] = ds; ssq[wid] = dq; }
        __syncthreads();
        if (tid == 0) {
            double a = 0.0, b = 0.0;
#pragma unroll
            for (int i = 0; i < 8; i++) { a += ssum[i]; b += ssq[i]; }
            atomicAdd(&d_stats[0], a);
            atomicAdd(&d_stats[1], b);
        }
    }
}

// ---------------- setup ------------------------------------------------------
__device__ void softmax_n(const float* in, float* out, int n) {
    float m = in[0];
    for (int i = 1; i < n; i++) m = fmaxf(m, in[i]);
    float s = 0.f;
    for (int i = 0; i < n; i++) { out[i] = expf(in[i] - m); s += out[i]; }
    float inv = 1.f / s;
    for (int i = 0; i < n; i++) out[i] *= inv;
}

__global__ void setup_kernel(const int* __restrict__ batch,
                             const float* __restrict__ na, const float* __restrict__ pl,
                             const float* __restrict__ ro, const float* __restrict__ la) {
    int i = blockIdx.x * blockDim.x + threadIdx.x;
    if (i <= GG) {
        int lo = 0, hi = NN;
        while (lo < hi) { int mid = (lo + hi) >> 1; if (batch[mid] < i) lo = mid + 1; else hi = mid; }
        d_gs[i] = lo;
    }
    if (i < NN) { d_kc[i] = 1.f; d_cnt[i] = 0; }
    if (i == 0) {
        for (int l = 0; l < LL; l++) softmax_n(na + l * 4, d_naa + l * 4, 4);
        for (int l = 0; l < LL; l++) softmax_n(pl + l * 3, d_pa + l * 3, 3);
        for (int l = 0; l < LL + 1; l++) softmax_n(ro + l * 3, d_roa + l * 3, 3);
        softmax_n(la, d_laa, 3);
    }
}

// x split -> d_Hn ; lin1 W -> d_B1 [n][k] split
__global__ void convert_kernel(const float* __restrict__ x, const float* __restrict__ W) {
    int idx = blockIdx.x * blockDim.x + threadIdx.x;
    if (idx < NHTOT) {
        float v = x[idx];
        __nv_bfloat16 h = __float2bfloat16(v);
        d_Hn[idx] = h;
        d_Hn[NPH + idx] = __float2bfloat16(v - __bfloat162float(h));
    } else if (idx < NHTOT + HSQ) {
        int i = idx - NHTOT;
        int k = i >> 7, n = i & 127;
        float v = W[k * HH + n];
        __nv_bfloat16 h = __float2bfloat16(v);
        d_B1[n * HH + k] = h;
        d_B1[HSQ + n * HH + k] = __float2bfloat16(v - __bfloat162float(h));
    }
}

__global__ void csr_count(const int* __restrict__ ei) {
    int e = blockIdx.x * blockDim.x + threadIdx.x;
    if (e >= EE) return;
    atomicAdd(&d_cnt[ei[EE + e]], 1);
}

__global__ void scan1() {
    __shared__ int sh[256];
    int i = blockIdx.x * 256 + threadIdx.x;
    int v = (i < NN) ? d_cnt[i] : 0;
    sh[threadIdx.x] = v;
    __syncthreads();
#pragma unroll
    for (int d = 1; d < 256; d <<= 1) {
        int t = (threadIdx.x >= d) ? sh[threadIdx.x - d] : 0;
        __syncthreads();
        sh[threadIdx.x] += t;
        __syncthreads();
    }
    if (i < NN) d_rp[i + 1] = sh[threadIdx.x];
    if (threadIdx.x == 255) d_bsum[blockIdx.x] = sh[255];
}

__global__ void scan2() {
    __shared__ int sh[256];
    int t = threadIdx.x;
    int v = (t < NB) ? d_bsum[t] : 0;
    sh[t] = v;
    __syncthreads();
#pragma unroll
    for (int d = 1; d < 256; d <<= 1) {
        int tv = (t >= d) ? sh[t - d] : 0;
        __syncthreads();
        sh[t] += tv;
        __syncthreads();
    }
    if (t < NB) d_bsum[t] = sh[t] - v;
}

__global__ void scan3() {
    int i = blockIdx.x * 256 + threadIdx.x;
    if (i < NN) d_rp[i + 1] += d_bsum[blockIdx.x];
    if (i == 0) d_rp[0] = 0;
}

__global__ void csr_fill(const int* __restrict__ ei) {
    int e = blockIdx.x * blockDim.x + threadIdx.x;
    if (e >= EE) return;
    int d = ei[EE + e];
    int old = atomicSub(&d_cnt[d], 1);
    d_colsrc[d_rp[d] + old - 1] = ei[e];
}

// combine_W + deg + stats zero
__global__ void combine_deg(const float* __restrict__ W, const float* __restrict__ na) {
    int idx = blockIdx.x * blockDim.x + threadIdx.x;
    if (idx == 0) { d_stats[0] = 0.0; d_stats[1] = 0.0; }
    if (idx < 4 * HSQ) {
        int k = idx >> 7, n = idx & 127;
        int p = k >> 7, kk = k & 127;
        int widx = kk * HH + n;
        float a0 = na[0], a1 = na[1], a2 = na[2], a3 = na[3];
        float v;
        if (p == 0)      v = a1 * W[2 * HSQ + widx] + a2 * W[3 * HSQ + widx] + a3 * W[4 * HSQ + widx];
        else if (p == 1) v = a2 * W[3 * HSQ + widx] + a3 * W[5 * HSQ + widx];
        else if (p == 2) v = a1 * W[1 * HSQ + widx];
        else             v = a0 * W[widx];
        __nv_bfloat16 h = __float2bfloat16(v);
        d_B[(size_t)n * KBIG + k] = h;
        d_B[KBIG * HH + (size_t)n * KBIG + k] = __float2bfloat16(v - __bfloat162float(h));
    } else {
        int n = idx - 4 * HSQ;
        if (n < NN) {
            float kcn = d_kc[n];
            float s = kcn;
            int b = d_rp[n], e = d_rp[n + 1];
            for (int p = b; p < e; p++) s += d_kc[d_colsrc[p]];
            float dg = fmaxf(kcn * s, 1e-6f);
            d_rdeg[n] = 1.f / dg;
            d_rs[n] = rsqrtf(dg);
        }
    }
}

// ---------------- gather aggregation ----------------------------------------
__global__ void aggregate_kernel(const float* __restrict__ h) {
    int gw = (blockIdx.x * blockDim.x + threadIdx.x) >> 5;
    int lane = threadIdx.x & 31;
    if (gw >= NN) return;
    float kcd = d_kc[gw];
    float rsd = d_rs[gw];
    float rdg = d_rdeg[gw];
    const float4* h4 = (const float4*)h;
    float4 hv = h4[(size_t)gw * 32 + lane];
    float wg = kcd * rsd;
    float4 as = {hv.x * kcd, hv.y * kcd, hv.z * kcd, hv.w * kcd};
    float4 ag = {hv.x * wg, hv.y * wg, hv.z * wg, hv.w * wg};
    int beg = d_rp[gw], end = d_rp[gw + 1];
    for (int p = beg; p < end; p++) {
        int s = d_colsrc[p];
        float w1 = d_kc[s];
        if (w1 != 0.f) {
            float rv = d_rs[s];
            float4 hs = h4[(size_t)s * 32 + lane];
            as.x += hs.x; as.y += hs.y; as.z += hs.z; as.w += hs.w;
            ag.x = fmaf(hs.x, rv, ag.x); ag.y = fmaf(hs.y, rv, ag.y);
            ag.z = fmaf(hs.z, rv, ag.z); ag.w = fmaf(hs.w, rv, ag.w);
        }
    }
    float fg = kcd * rsd;
    as.x *= kcd; as.y *= kcd; as.z *= kcd; as.w *= kcd;
    ag.x *= fg;  ag.y *= fg;  ag.z *= fg;  ag.w *= fg;
    float4 asr = {as.x * rdg, as.y * rdg, as.z * rdg, as.w * rdg};
    size_t idx = (size_t)gw * HH + lane * 4;
    split_store4(d_A + 2ULL * NPH, d_A + 3ULL * NPH, idx, as);
    split_store4(d_A + 4ULL * NPH, d_A + 5ULL * NPH, idx, asr);
    split_store4(d_A + 6ULL * NPH, d_A + 7ULL * NPH, idx, ag);
}

// ---------------- layernorm + gate + pool (reads d_Hn split) ----------------
__global__ void gate_kernel(float* __restrict__ h, const float* __restrict__ p0,
                            const float* __restrict__ pa) {
    int gw = (blockIdx.x * blockDim.x + threadIdx.x) >> 5;
    int lane = threadIdx.x & 31;
    if (gw >= NN) return;
    const double invc = 1.0 / ((double)NN * (double)HH);
    double md = d_stats[0] * invc;
    double vd = d_stats[1] * invc - md * md;
    float mean = (float)md;
    float inv = rsqrtf((float)vd + 1e-5f);
    size_t idx = (size_t)gw * HH + lane * 4;
    __nv_bfloat162 hh0 = *(const __nv_bfloat162*)&d_Hn[idx];
    __nv_bfloat162 hh1 = *(const __nv_bfloat162*)&d_Hn[idx + 2];
    __nv_bfloat162 hl0 = *(const __nv_bfloat162*)&d_Hn[NPH + idx];
    __nv_bfloat162 hl1 = *(const __nv_bfloat162*)&d_Hn[NPH + idx + 2];
    float2 fh0 = __bfloat1622float2(hh0), fh1 = __bfloat1622float2(hh1);
    float2 fl0 = __bfloat1622float2(hl0), fl1 = __bfloat1622float2(hl1);
    float4 hv = {fh0.x + fl0.x, fh0.y + fl0.y, fh1.x + fl1.x, fh1.y + fl1.y};
    float4 hn;
    hn.x = (hv.x - mean) * inv; hn.y = (hv.y - mean) * inv;
    hn.z = (hv.z - mean) * inv; hn.w = (hv.w - mean) * inv;
    float4 a = ((const float4*)p0)[lane];
    float4 b = ((const float4*)(p0 + HH))[lane];
    float d0 = hn.x * a.x + hn.y * a.y + hn.z * a.z + hn.w * a.w;
    float d1 = hn.x * b.x + hn.y * b.y + hn.z * b.z + hn.w * b.w;
#pragma unroll
    for (int o = 16; o; o >>= 1) {
        d0 += __shfl_xor_sync(0xffffffffu, d0, o);
        d1 += __shfl_xor_sync(0xffffffffu, d1, o);
    }
    float g1 = 1.f / (1.f + expf(-d0));
    float g2 = tanhf(d1);
    float gate = pa[0] * g1 + pa[1] * g2 + pa[2];
    float kv = gate > 0.01f ? 1.f : 0.f;
    float sc = gate * kv;
    hn.x *= sc; hn.y *= sc; hn.z *= sc; hn.w *= sc;
    ((float4*)h)[(size_t)gw * 32 + lane] = hn;
    split_store4(d_A, d_A + NPH, idx, hn);
    if (lane == 0) d_kc[gw] *= kv;
}

// ---------------- readout ----------------------------------------------------
__global__ void readout_kernel(const float* __restrict__ h, int r) {
    int g = blockIdx.x, k = threadIdx.x;
    int b = d_gs[g], e = d_gs[g + 1];
    float s = 0.f, mx = -INFINITY;
    for (int n = b; n < e; n++) {
        float v = h[(size_t)n * HH + k];
        s += v;
        mx = fmaxf(mx, v);
    }
    float c = (float)(e - b);
    float mean = s / fmaxf(c, 1.f);
    if (e == b) mx = 0.f;
    const float* w = d_roa + r * 3;
    d_reps[((size_t)r * GG + g) * HH + k] = w[0] * mean + w[1] * mx + w[2] * s;
}

// ---------------- final head -------------------------------------------------
__global__ void final_head(const float* __restrict__ Wo, const float* __restrict__ bo,
                           const float* __restrict__ Wc, const float* __restrict__ bc,
                           float* __restrict__ out) {
    __shared__ float zr[HH];
    __shared__ float z2[HH];
    __shared__ float lg[OUTC];
    __shared__ float s_lse;
    int g = blockIdx.x, k = threadIdx.x;
    int idx = g * HH + k;
    float r0 = d_reps[idx];
    float r1 = d_reps[GG * HH + idx];
    float r2 = d_reps[2 * GG * HH + idx];
    float r3 = d_reps[3 * GG * HH + idx];
    float s = r0 + r1 + r2 + r3;
    float mx = fmaxf(fmaxf(r0, r1), fmaxf(r2, r3));
    zr[k] = d_laa[0] * eluf(s) + d_laa[1] * eluf(s * 0.25f) + d_laa[2] * eluf(mx);
    __syncthreads();
    float acc = bo[k];
    for (int k2 = 0; k2 < HH; k2++) acc = fmaf(zr[k2], Wo[k2 * HH + k], acc);
    z2[k] = eluf(acc);
    __syncthreads();
    if (k < OUTC) {
        float accl = bc[k];
        for (int k2 = 0; k2 < HH; k2++) accl = fmaf(z2[k2], Wc[k2 * OUTC + k], accl);
        lg[k] = accl;
    }
    __syncthreads();
    if (k == 0) {
        float m = lg[0];
        for (int i = 1; i < OUTC; i++) m = fmaxf(m, lg[i]);
        float se = 0.f;
        for (int i = 0; i < OUTC; i++) se += expf(lg[i] - m);
        s_lse = m + logf(se);
    }
    __syncthreads();
    if (k < OUTC) out[g * OUTC + k] = lg[k] - s_lse;
}

// ---------------- launch ------------------------------------------------------
extern "C" void kernel_launch(void* const* d_in, const int* in_sizes, int n_in,
                              void* d_out, int out_size) {
    const float* x         = (const float*)d_in[0];
    const int*   ei        = (const int*)d_in[1];
    const int*   batch     = (const int*)d_in[2];
    const float* lin1_W    = (const float*)d_in[3];
    const float* lin1_b    = (const float*)d_in[4];
    const float* gnn_W     = (const float*)d_in[5];
    const float* pool_p    = (const float*)d_in[6];
    const float* lin_out_W = (const float*)d_in[7];
    const float* lin_out_b = (const float*)d_in[8];
    const float* cls_W     = (const float*)d_in[9];
    const float* cls_b     = (const float*)d_in[10];
    const float* na_log    = (const float*)d_in[11];
    const float* pool_log  = (const float*)d_in[12];
    const float* ro_log    = (const float*)d_in[13];
    const float* la_log    = (const float*)d_in[14];
    float* out = (float*)d_out;

    float *bufA, *bufB, *naa, *pa;
    __nv_bfloat16 *Ab, *Hnb, *Bb, *B1b;
    cudaGetSymbolAddress((void**)&bufA, d_bufA);
    cudaGetSymbolAddress((void**)&bufB, d_bufB);
    cudaGetSymbolAddress((void**)&naa, d_naa);
    cudaGetSymbolAddress((void**)&pa, d_pa);
    cudaGetSymbolAddress((void**)&Ab, d_A);
    cudaGetSymbolAddress((void**)&Hnb, d_Hn);
    cudaGetSymbolAddress((void**)&Bb, d_B);
    cudaGetSymbolAddress((void**)&B1b, d_B1);

    cudaFuncSetAttribute(gemm_mma<4, 0>, cudaFuncAttributeMaxDynamicSharedMemorySize, SM_TOTAL);
    cudaFuncSetAttribute(gemm_mma<16, 1>, cudaFuncAttributeMaxDynamicSharedMemorySize, SM_TOTAL);

    const int GB = ((NN + 127) / 128) * 2;   // 782: 2 n-tiles per 128-row block
    const int EB = (EE + 255) / 256;
    const int WB = (NN * 32 + 255) / 256;
    const int NBK = (NN + 255) / 256;

    setup_kernel<<<NBK, 256>>>(batch, na_log, pool_log, ro_log, la_log);
    convert_kernel<<<(NHTOT + HSQ + 255) / 256, 256>>>(x, lin1_W);
    csr_count<<<EB, 256>>>(ei);
    // launch #4 = profiled slot: lin1 GEMM (reads d_Hn x-split, writes bufA + chunk0 split)
    gemm_mma<4, 0><<<GB, 256, SM_TOTAL>>>(Hnb, B1b, bufA, Ab, lin1_b);
    scan1<<<NBK, 256>>>();
    scan2<<<1, 256>>>();
    scan3<<<NBK, 256>>>();
    csr_fill<<<EB, 256>>>(ei);
    readout_kernel<<<GG, HH>>>(bufA, 0);

    float* hcur = bufA;
    float* hnew = bufB;
    for (int i = 0; i < LL; i++) {
        const float* Wi = gnn_W + (size_t)i * 6 * HSQ;
        combine_deg<<<(4 * HSQ + NN + 255) / 256, 256>>>(Wi, naa + i * 4);
        aggregate_kernel<<<WB, 256>>>(hcur);
        gemm_mma<16, 1><<<GB, 256, SM_TOTAL>>>(Ab, Bb, nullptr, Hnb, nullptr);
        gate_kernel<<<WB, 256>>>(hnew, pool_p + (size_t)i * 2 * HH, pa + i * 3);
        readout_kernel<<<GG, HH>>>(hnew, i + 1);
        float* t = hcur; hcur = hnew; hnew = t;
    }

    final_head<<<GG, HH>>>(lin_out_W, lin_out_b, cls_W, cls_b, out);
}

// round 11
// speedup vs baseline: 1.0716x; 1.0107x over previous
#include <cuda_runtime.h>
#include <cuda_bf16.h>
#include <math.h>
#include <cstdint>

#define NN 50000
#define EE 800000
#define GG 512
#define HH 128
#define LL 3
#define OUTC 10
#define NHTOT (NN * HH)
#define HSQ (HH * HH)
#define NB ((NN + 255) / 256)
#define KBIG 512
#define NP 50176
#define NPH (NP * HH)

// ---------------- scratch (device globals) ----------------------------------
__device__ float  d_bufA[NHTOT];
__device__ float  d_bufB[NHTOT];
__device__ float  d_kc[NN];
__device__ float  d_rs[NN];
__device__ float  d_rdeg[NN];
__device__ int    d_rp[NN + 1];
__device__ int    d_cnt[NN];
__device__ int    d_bsum[NB];
__device__ int    d_colsrc[EE];
__device__ float  d_reps[(LL + 1) * GG * HH];
// GEMM input planes: chunk c (0=h,1=s,2=sr,3=g): hi at 2c*NPH, lo at (2c+1)*NPH
__device__ __nv_bfloat16 d_A[8ULL * NPH];
// GEMM output / x-input planes: hi at 0, lo at NPH
__device__ __nv_bfloat16 d_Hn[2ULL * NPH];
__device__ __nv_bfloat16 d_B[2 * KBIG * HH];   // [n][k] hi block then lo block
__device__ __nv_bfloat16 d_B1[2 * HSQ];        // lin1 W [n][k] hi then lo
__device__ int    d_gs[GG + 1];
__device__ float  d_naa[LL * 4];
__device__ float  d_pa[LL * 3];
__device__ float  d_roa[(LL + 1) * 3];
__device__ float  d_laa[3];
__device__ double d_stats[2];

__device__ __forceinline__ float eluf(float x) { return x > 0.f ? x : expm1f(x); }

__device__ __forceinline__ uint32_t smem_u32(const void* p) {
    uint32_t a;
    asm("{ .reg .u64 t; cvta.to.shared.u64 t, %1; cvt.u32.u64 %0, t; }" : "=r"(a) : "l"(p));
    return a;
}

__device__ __forceinline__ void ldm_x4(uint32_t r[4], uint32_t addr) {
    asm volatile("ldmatrix.sync.aligned.m8n8.x4.shared.b16 {%0,%1,%2,%3}, [%4];"
                 : "=r"(r[0]), "=r"(r[1]), "=r"(r[2]), "=r"(r[3]) : "r"(addr));
}

__device__ __forceinline__ void mma_bf16(float c[4], const uint32_t a[4],
                                         uint32_t b0, uint32_t b1) {
    asm volatile(
        "mma.sync.aligned.m16n8k16.row.col.f32.bf16.bf16.f32 "
        "{%0,%1,%2,%3},{%4,%5,%6,%7},{%8,%9},{%0,%1,%2,%3};"
        : "+f"(c[0]), "+f"(c[1]), "+f"(c[2]), "+f"(c[3])
        : "r"(a[0]), "r"(a[1]), "r"(a[2]), "r"(a[3]), "r"(b0), "r"(b1));
}

#define CP_ASYNC16(dst, src) asm volatile("cp.async.cg.shared.global [%0], [%1], 16;" :: "r"(dst), "l"(src))
#define CP_COMMIT()          asm volatile("cp.async.commit_group;")
#define CP_WAIT(n)           asm volatile("cp.async.wait_group %0;" :: "n"(n))

// 64B-row smem tile (32 bf16/row), XOR swizzle; addr(k0+16) = addr(k0) ^ 32
__device__ __forceinline__ uint32_t swz32(int row, int col) {
    return (uint32_t)(row * 64 + ((((col >> 3) ^ ((row >> 1) & 3))) << 4));
}

__device__ __forceinline__ void split_store4(__nv_bfloat16* hi, __nv_bfloat16* lo,
                                             size_t idx, float4 v) {
    __nv_bfloat162 h0 = __floats2bfloat162_rn(v.x, v.y);
    __nv_bfloat162 h1 = __floats2bfloat162_rn(v.z, v.w);
    float2 f0 = __bfloat1622float2(h0), f1 = __bfloat1622float2(h1);
    *(__nv_bfloat162*)&hi[idx]     = h0;
    *(__nv_bfloat162*)&hi[idx + 2] = h1;
    *(__nv_bfloat162*)&lo[idx]     = __floats2bfloat162_rn(v.x - f0.x, v.y - f0.y);
    *(__nv_bfloat162*)&lo[idx + 2] = __floats2bfloat162_rn(v.z - f1.x, v.w - f1.y);
}

// stage: AHI(8K) ALO(8K) BHI(4K) BLO(4K) = 24KB; 3 stages = 72KB; 3 CTAs = 216KB/SM
#define STG_SZ   24576
#define OFF_ALO  8192
#define OFF_BHI  16384
#define OFF_BLO  20480
#define SM_TOTAL 73728

// ---------------- tensor-core GEMM ------------------------------------------
// CTA tile 128(m) x 64(n); warp grid 4m x 2n; warp tile 32x32 (acc = 32 regs).
// MODE 0: bias+elu, writes fp32 C + split Csp.   MODE 1: elu + LN stats, split Csp only.
template <int NSLICES, int MODE>
__global__ void __launch_bounds__(256, 3) gemm_mma(
    const __nv_bfloat16* __restrict__ A, const __nv_bfloat16* __restrict__ B,
    float* __restrict__ C, __nv_bfloat16* __restrict__ Csp,
    const float* __restrict__ bias) {
    extern __shared__ char smem[];
    uint32_t sb = smem_u32(smem);
    const int tid = threadIdx.x;
    const int wid = tid >> 5, lane = tid & 31;
    const int warp_m = wid & 3, warp_n = wid >> 2;   // 4m x 2n
    const int bm = (blockIdx.x >> 1) * 128;
    const int bn = (blockIdx.x & 1) * 64;
    const int KB = NSLICES * 32;
    const int BLO = KB * 128;

    // --- loader mapping
    const int lrow = tid >> 1;
    const int lc = (tid & 1) * 8;
    const int brr = tid >> 2;
    const int bcc = (tid & 3) * 8;
    const uint32_t sA0 = swz32(lrow, lc);
    const uint32_t sA1 = swz32(lrow, lc + 16);
    const uint32_t sB  = OFF_BHI + swz32(brr, bcc);
    const __nv_bfloat16* Abase = A + (size_t)(bm + lrow) * HH + lc;
    const __nv_bfloat16* Bbase = B + (size_t)(bn + brr) * KB + bcc;

    // --- compute mapping
    const int lr = lane & 15, lg2 = (lane >> 4) * 8;
    const int m_base = warp_m * 32;
    const int n_base = warp_n * 32;
    uint32_t aoff[2], boff[2];
#pragma unroll
    for (int mt = 0; mt < 2; mt++) aoff[mt] = swz32(m_base + mt * 16 + lr, lg2);
#pragma unroll
    for (int np = 0; np < 2; np++) boff[np] = OFF_BHI + swz32(n_base + np * 16 + lr, lg2);

    float acc[2][4][4];
#pragma unroll
    for (int i = 0; i < 2; i++)
#pragma unroll
        for (int j = 0; j < 4; j++)
#pragma unroll
            for (int q = 0; q < 4; q++) acc[i][j][q] = 0.f;

#pragma unroll
    for (int pf = 0; pf < 2; pf++) {
        const __nv_bfloat16* ap = Abase + (size_t)(pf >> 2) * (2 * (size_t)NPH) + (pf & 3) * 32;
        const __nv_bfloat16* bp = Bbase + pf * 32;
        uint32_t base = sb + pf * STG_SZ;
        CP_ASYNC16(base + sA0, ap);
        CP_ASYNC16(base + sA1, ap + 16);
        CP_ASYNC16(base + sA0 + OFF_ALO, ap + NPH);
        CP_ASYNC16(base + sA1 + OFF_ALO, ap + NPH + 16);
        CP_ASYNC16(base + sB, bp);
        CP_ASYNC16(base + sB + (OFF_BLO - OFF_BHI), bp + BLO);
        CP_COMMIT();
    }

#pragma unroll
    for (int s = 0; s < NSLICES; s++) {
        if (s + 1 < NSLICES) { CP_WAIT(1); } else { CP_WAIT(0); }
        __syncthreads();
        if (s + 2 < NSLICES) {
            const int sn = s + 2;
            const __nv_bfloat16* ap = Abase + (size_t)(sn >> 2) * (2 * (size_t)NPH) + (sn & 3) * 32;
            const __nv_bfloat16* bp = Bbase + sn * 32;
            uint32_t base = sb + (sn % 3) * STG_SZ;
            CP_ASYNC16(base + sA0, ap);
            CP_ASYNC16(base + sA1, ap + 16);
            CP_ASYNC16(base + sA0 + OFF_ALO, ap + NPH);
            CP_ASYNC16(base + sA1 + OFF_ALO, ap + NPH + 16);
            CP_ASYNC16(base + sB, bp);
            CP_ASYNC16(base + sB + (OFF_BLO - OFF_BHI), bp + BLO);
            CP_COMMIT();
        }
        const uint32_t sbase = sb + (uint32_t)((s % 3) * STG_SZ);
#pragma unroll
        for (int ks = 0; ks < 2; ks++) {
            const uint32_t kx = ks * 32;
            uint32_t bhm[2][4], blm[2][4];
#pragma unroll
            for (int np = 0; np < 2; np++) {
                uint32_t ad = sbase + (boff[np] ^ kx);
                ldm_x4(bhm[np], ad);
                ldm_x4(blm[np], ad + (OFF_BLO - OFF_BHI));
            }
#pragma unroll
            for (int mt = 0; mt < 2; mt++) {
                uint32_t ad = sbase + (aoff[mt] ^ kx);
                uint32_t ah[4], al[4];
                ldm_x4(ah, ad);
                ldm_x4(al, ad + OFF_ALO);
#pragma unroll
                for (int nt = 0; nt < 4; nt++) {
                    int np = nt >> 1, sel = nt & 1;
                    uint32_t b0h = sel ? bhm[np][1] : bhm[np][0];
                    uint32_t b1h = sel ? bhm[np][3] : bhm[np][2];
                    uint32_t b0l = sel ? blm[np][1] : blm[np][0];
                    uint32_t b1l = sel ? blm[np][3] : blm[np][2];
                    mma_bf16(acc[mt][nt], ah, b0h, b1h);
                    mma_bf16(acc[mt][nt], al, b0h, b1h);
                    mma_bf16(acc[mt][nt], ah, b0l, b1l);
                }
            }
        }
    }
    __syncthreads();

    // ---- epilogue
    float lsum = 0.f, lsq = 0.f;
    int rq = lane >> 2, cq = (lane & 3) * 2;
#pragma unroll
    for (int mt = 0; mt < 2; mt++) {
#pragma unroll
        for (int half = 0; half < 2; half++) {
            int gm = bm + m_base + mt * 16 + rq + half * 8;
            if (gm >= NN) continue;
#pragma unroll
            for (int nt = 0; nt < 4; nt++) {
                int col = bn + n_base + nt * 8 + cq;
                float v0 = acc[mt][nt][half * 2];
                float v1 = acc[mt][nt][half * 2 + 1];
                if (MODE == 0) {
                    v0 = eluf(v0 + bias[col]);
                    v1 = eluf(v1 + bias[col + 1]);
                    *(float2*)&C[(size_t)gm * HH + col] = make_float2(v0, v1);
                } else {
                    v0 = eluf(v0); v1 = eluf(v1);
                    lsum += v0 + v1;
                    lsq = fmaf(v0, v0, lsq); lsq = fmaf(v1, v1, lsq);
                }
                __nv_bfloat162 h = __floats2bfloat162_rn(v0, v1);
                float2 hf = __bfloat1622float2(h);
                size_t ci = (size_t)gm * HH + col;
                *(__nv_bfloat162*)&Csp[ci] = h;
                *(__nv_bfloat162*)&Csp[NPH + ci] =
                    __floats2bfloat162_rn(v0 - hf.x, v1 - hf.y);
            }
        }
    }
    if (MODE == 1) {
        double ds = (double)lsum, dq = (double)lsq;
#pragma unroll
        for (int o = 16; o; o >>= 1) {
            ds += __shfl_down_sync(0xffffffffu, ds, o);
            dq += __shfl_down_sync(0xffffffffu, dq, o);
        }
        __shared__ double ssum[8], ssq[8];
        if (lane == 0) { ssum[wid] = ds; ssq[wid] = dq; }
        __syncthreads();
        if (tid == 0) {
            double a = 0.0, b = 0.0;
#pragma unroll
            for (int i = 0; i < 8; i++) { a += ssum[i]; b += ssq[i]; }
            atomicAdd(&d_stats[0], a);
            atomicAdd(&d_stats[1], b);
        }
    }
}

// ---------------- setup ------------------------------------------------------
__device__ void softmax_n(const float* in, float* out, int n) {
    float m = in[0];
    for (int i = 1; i < n; i++) m = fmaxf(m, in[i]);
    float s = 0.f;
    for (int i = 0; i < n; i++) { out[i] = expf(in[i] - m); s += out[i]; }
    float inv = 1.f / s;
    for (int i = 0; i < n; i++) out[i] *= inv;
}

__global__ void setup_kernel(const int* __restrict__ batch,
                             const float* __restrict__ na, const float* __restrict__ pl,
                             const float* __restrict__ ro, const float* __restrict__ la) {
    int i = blockIdx.x * blockDim.x + threadIdx.x;
    if (i <= GG) {
        int lo = 0, hi = NN;
        while (lo < hi) { int mid = (lo + hi) >> 1; if (batch[mid] < i) lo = mid + 1; else hi = mid; }
        d_gs[i] = lo;
    }
    if (i < NN) { d_kc[i] = 1.f; d_cnt[i] = 0; }
    if (i == 0) {
        for (int l = 0; l < LL; l++) softmax_n(na + l * 4, d_naa + l * 4, 4);
        for (int l = 0; l < LL; l++) softmax_n(pl + l * 3, d_pa + l * 3, 3);
        for (int l = 0; l < LL + 1; l++) softmax_n(ro + l * 3, d_roa + l * 3, 3);
        softmax_n(la, d_laa, 3);
    }
}

__global__ void convert_kernel(const float* __restrict__ x, const float* __restrict__ W) {
    int idx = blockIdx.x * blockDim.x + threadIdx.x;
    if (idx < NHTOT) {
        float v = x[idx];
        __nv_bfloat16 h = __float2bfloat16(v);
        d_Hn[idx] = h;
        d_Hn[NPH + idx] = __float2bfloat16(v - __bfloat162float(h));
    } else if (idx < NHTOT + HSQ) {
        int i = idx - NHTOT;
        int k = i >> 7, n = i & 127;
        float v = W[k * HH + n];
        __nv_bfloat16 h = __float2bfloat16(v);
        d_B1[n * HH + k] = h;
        d_B1[HSQ + n * HH + k] = __float2bfloat16(v - __bfloat162float(h));
    }
}

__global__ void csr_count(const int* __restrict__ ei) {
    int e = blockIdx.x * blockDim.x + threadIdx.x;
    if (e >= EE) return;
    atomicAdd(&d_cnt[ei[EE + e]], 1);
}

__global__ void scan1() {
    __shared__ int sh[256];
    int i = blockIdx.x * 256 + threadIdx.x;
    int v = (i < NN) ? d_cnt[i] : 0;
    sh[threadIdx.x] = v;
    __syncthreads();
#pragma unroll
    for (int d = 1; d < 256; d <<= 1) {
        int t = (threadIdx.x >= d) ? sh[threadIdx.x - d] : 0;
        __syncthreads();
        sh[threadIdx.x] += t;
        __syncthreads();
    }
    if (i < NN) d_rp[i + 1] = sh[threadIdx.x];
    if (threadIdx.x == 255) d_bsum[blockIdx.x] = sh[255];
}

__global__ void scan2() {
    __shared__ int sh[256];
    int t = threadIdx.x;
    int v = (t < NB) ? d_bsum[t] : 0;
    sh[t] = v;
    __syncthreads();
#pragma unroll
    for (int d = 1; d < 256; d <<= 1) {
        int tv = (t >= d) ? sh[t - d] : 0;
        __syncthreads();
        sh[t] += tv;
        __syncthreads();
    }
    if (t < NB) d_bsum[t] = sh[t] - v;
}

__global__ void scan3() {
    int i = blockIdx.x * 256 + threadIdx.x;
    if (i < NN) d_rp[i + 1] += d_bsum[blockIdx.x];
    if (i == 0) d_rp[0] = 0;
}

__global__ void csr_fill(const int* __restrict__ ei) {
    int e = blockIdx.x * blockDim.x + threadIdx.x;
    if (e >= EE) return;
    int d = ei[EE + e];
    int old = atomicSub(&d_cnt[d], 1);
    d_colsrc[d_rp[d] + old - 1] = ei[e];
}

// combine_W + deg + stats zero
__global__ void combine_deg(const float* __restrict__ W, const float* __restrict__ na) {
    int idx = blockIdx.x * blockDim.x + threadIdx.x;
    if (idx == 0) { d_stats[0] = 0.0; d_stats[1] = 0.0; }
    if (idx < 4 * HSQ) {
        int k = idx >> 7, n = idx & 127;
        int p = k >> 7, kk = k & 127;
        int widx = kk * HH + n;
        float a0 = na[0], a1 = na[1], a2 = na[2], a3 = na[3];
        float v;
        if (p == 0)      v = a1 * W[2 * HSQ + widx] + a2 * W[3 * HSQ + widx] + a3 * W[4 * HSQ + widx];
        else if (p == 1) v = a2 * W[3 * HSQ + widx] + a3 * W[5 * HSQ + widx];
        else if (p == 2) v = a1 * W[1 * HSQ + widx];
        else             v = a0 * W[widx];
        __nv_bfloat16 h = __float2bfloat16(v);
        d_B[(size_t)n * KBIG + k] = h;
        d_B[KBIG * HH + (size_t)n * KBIG + k] = __float2bfloat16(v - __bfloat162float(h));
    } else {
        int n = idx - 4 * HSQ;
        if (n < NN) {
            float kcn = d_kc[n];
            float s = kcn;
            int b = d_rp[n], e = d_rp[n + 1];
            for (int p = b; p < e; p++) s += d_kc[d_colsrc[p]];
            float dg = fmaxf(kcn * s, 1e-6f);
            d_rdeg[n] = 1.f / dg;
            d_rs[n] = rsqrtf(dg);
        }
    }
}

// ---------------- gather aggregation ----------------------------------------
__global__ void aggregate_kernel(const float* __restrict__ h) {
    int gw = (blockIdx.x * blockDim.x + threadIdx.x) >> 5;
    int lane = threadIdx.x & 31;
    if (gw >= NN) return;
    float kcd = d_kc[gw];
    float rsd = d_rs[gw];
    float rdg = d_rdeg[gw];
    const float4* h4 = (const float4*)h;
    float4 hv = h4[(size_t)gw * 32 + lane];
    float wg = kcd * rsd;
    float4 as = {hv.x * kcd, hv.y * kcd, hv.z * kcd, hv.w * kcd};
    float4 ag = {hv.x * wg, hv.y * wg, hv.z * wg, hv.w * wg};
    int beg = d_rp[gw], end = d_rp[gw + 1];
    for (int p = beg; p < end; p++) {
        int s = d_colsrc[p];
        float w1 = d_kc[s];
        if (w1 != 0.f) {
            float rv = d_rs[s];
            float4 hs = h4[(size_t)s * 32 + lane];
            as.x += hs.x; as.y += hs.y; as.z += hs.z; as.w += hs.w;
            ag.x = fmaf(hs.x, rv, ag.x); ag.y = fmaf(hs.y, rv, ag.y);
            ag.z = fmaf(hs.z, rv, ag.z); ag.w = fmaf(hs.w, rv, ag.w);
        }
    }
    float fg = kcd * rsd;
    as.x *= kcd; as.y *= kcd; as.z *= kcd; as.w *= kcd;
    ag.x *= fg;  ag.y *= fg;  ag.z *= fg;  ag.w *= fg;
    float4 asr = {as.x * rdg, as.y * rdg, as.z * rdg, as.w * rdg};
    size_t idx = (size_t)gw * HH + lane * 4;
    split_store4(d_A + 2ULL * NPH, d_A + 3ULL * NPH, idx, as);
    split_store4(d_A + 4ULL * NPH, d_A + 5ULL * NPH, idx, asr);
    split_store4(d_A + 6ULL * NPH, d_A + 7ULL * NPH, idx, ag);
}

// ---------------- layernorm + gate + pool (reads d_Hn split) ----------------
__global__ void gate_kernel(float* __restrict__ h, const float* __restrict__ p0,
                            const float* __restrict__ pa) {
    int gw = (blockIdx.x * blockDim.x + threadIdx.x) >> 5;
    int lane = threadIdx.x & 31;
    if (gw >= NN) return;
    const double invc = 1.0 / ((double)NN * (double)HH);
    double md = d_stats[0] * invc;
    double vd = d_stats[1] * invc - md * md;
    float mean = (float)md;
    float inv = rsqrtf((float)vd + 1e-5f);
    size_t idx = (size_t)gw * HH + lane * 4;
    __nv_bfloat162 hh0 = *(const __nv_bfloat162*)&d_Hn[idx];
    __nv_bfloat162 hh1 = *(const __nv_bfloat162*)&d_Hn[idx + 2];
    __nv_bfloat162 hl0 = *(const __nv_bfloat162*)&d_Hn[NPH + idx];
    __nv_bfloat162 hl1 = *(const __nv_bfloat162*)&d_Hn[NPH + idx + 2];
    float2 fh0 = __bfloat1622float2(hh0), fh1 = __bfloat1622float2(hh1);
    float2 fl0 = __bfloat1622float2(hl0), fl1 = __bfloat1622float2(hl1);
    float4 hv = {fh0.x + fl0.x, fh0.y + fl0.y, fh1.x + fl1.x, fh1.y + fl1.y};
    float4 hn;
    hn.x = (hv.x - mean) * inv; hn.y = (hv.y - mean) * inv;
    hn.z = (hv.z - mean) * inv; hn.w = (hv.w - mean) * inv;
    float4 a = ((const float4*)p0)[lane];
    float4 b = ((const float4*)(p0 + HH))[lane];
    float d0 = hn.x * a.x + hn.y * a.y + hn.z * a.z + hn.w * a.w;
    float d1 = hn.x * b.x + hn.y * b.y + hn.z * b.z + hn.w * b.w;
#pragma unroll
    for (int o = 16; o; o >>= 1) {
        d0 += __shfl_xor_sync(0xffffffffu, d0, o);
        d1 += __shfl_xor_sync(0xffffffffu, d1, o);
    }
    float g1 = 1.f / (1.f + expf(-d0));
    float g2 = tanhf(d1);
    float gate = pa[0] * g1 + pa[1] * g2 + pa[2];
    float kv = gate > 0.01f ? 1.f : 0.f;
    float sc = gate * kv;
    hn.x *= sc; hn.y *= sc; hn.z *= sc; hn.w *= sc;
    ((float4*)h)[(size_t)gw * 32 + lane] = hn;
    split_store4(d_A, d_A + NPH, idx, hn);
    if (lane == 0) d_kc[gw] *= kv;
}

// ---------------- readout ----------------------------------------------------
__global__ void readout_kernel(const float* __restrict__ h, int r) {
    int g = blockIdx.x, k = threadIdx.x;
    int b = d_gs[g], e = d_gs[g + 1];
    float s = 0.f, mx = -INFINITY;
    for (int n = b; n < e; n++) {
        float v = h[(size_t)n * HH + k];
        s += v;
        mx = fmaxf(mx, v);
    }
    float c = (float)(e - b);
    float mean = s / fmaxf(c, 1.f);
    if (e == b) mx = 0.f;
    const float* w = d_roa + r * 3;
    d_reps[((size_t)r * GG + g) * HH + k] = w[0] * mean + w[1] * mx + w[2] * s;
}

// ---------------- final head -------------------------------------------------
__global__ void final_head(const float* __restrict__ Wo, const float* __restrict__ bo,
                           const float* __restrict__ Wc, const float* __restrict__ bc,
                           float* __restrict__ out) {
    __shared__ float zr[HH];
    __shared__ float z2[HH];
    __shared__ float lg[OUTC];
    __shared__ float s_lse;
    int g = blockIdx.x, k = threadIdx.x;
    int idx = g * HH + k;
    float r0 = d_reps[idx];
    float r1 = d_reps[GG * HH + idx];
    float r2 = d_reps[2 * GG * HH + idx];
    float r3 = d_reps[3 * GG * HH + idx];
    float s = r0 + r1 + r2 + r3;
    float mx = fmaxf(fmaxf(r0, r1), fmaxf(r2, r3));
    zr[k] = d_laa[0] * eluf(s) + d_laa[1] * eluf(s * 0.25f) + d_laa[2] * eluf(mx);
    __syncthreads();
    float acc = bo[k];
    for (int k2 = 0; k2 < HH; k2++) acc = fmaf(zr[k2], Wo[k2 * HH + k], acc);
    z2[k] = eluf(acc);
    __syncthreads();
    if (k < OUTC) {
        float accl = bc[k];
        for (int k2 = 0; k2 < HH; k2++) accl = fmaf(z2[k2], Wc[k2 * OUTC + k], accl);
        lg[k] = accl;
    }
    __syncthreads();
    if (k == 0) {
        float m = lg[0];
        for (int i = 1; i < OUTC; i++) m = fmaxf(m, lg[i]);
        float se = 0.f;
        for (int i = 0; i < OUTC; i++) se += expf(lg[i] - m);
        s_lse = m + logf(se);
    }
    __syncthreads();
    if (k < OUTC) out[g * OUTC + k] = lg[k] - s_lse;
}

// ---------------- launch ------------------------------------------------------
extern "C" void kernel_launch(void* const* d_in, const int* in_sizes, int n_in,
                              void* d_out, int out_size) {
    const float* x         = (const float*)d_in[0];
    const int*   ei        = (const int*)d_in[1];
    const int*   batch     = (const int*)d_in[2];
    const float* lin1_W    = (const float*)d_in[3];
    const float* lin1_b    = (const float*)d_in[4];
    const float* gnn_W     = (const float*)d_in[5];
    const float* pool_p    = (const float*)d_in[6];
    const float* lin_out_W = (const float*)d_in[7];
    const float* lin_out_b = (const float*)d_in[8];
    const float* cls_W     = (const float*)d_in[9];
    const float* cls_b     = (const float*)d_in[10];
    const float* na_log    = (const float*)d_in[11];
    const float* pool_log  = (const float*)d_in[12];
    const float* ro_log    = (const float*)d_in[13];
    const float* la_log    = (const float*)d_in[14];
    float* out = (float*)d_out;

    float *bufA, *bufB, *naa, *pa;
    __nv_bfloat16 *Ab, *Hnb, *Bb, *B1b;
    cudaGetSymbolAddress((void**)&bufA, d_bufA);
    cudaGetSymbolAddress((void**)&bufB, d_bufB);
    cudaGetSymbolAddress((void**)&naa, d_naa);
    cudaGetSymbolAddress((void**)&pa, d_pa);
    cudaGetSymbolAddress((void**)&Ab, d_A);
    cudaGetSymbolAddress((void**)&Hnb, d_Hn);
    cudaGetSymbolAddress((void**)&Bb, d_B);
    cudaGetSymbolAddress((void**)&B1b, d_B1);

    cudaFuncSetAttribute(gemm_mma<4, 0>, cudaFuncAttributeMaxDynamicSharedMemorySize, SM_TOTAL);
    cudaFuncSetAttribute(gemm_mma<16, 1>, cudaFuncAttributeMaxDynamicSharedMemorySize, SM_TOTAL);

    const int GB = ((NN + 127) / 128) * 2;   // 782
    const int EB = (EE + 255) / 256;
    const int WB = (NN * 32 + 255) / 256;
    const int NBK = (NN + 255) / 256;

    setup_kernel<<<NBK, 256>>>(batch, na_log, pool_log, ro_log, la_log);
    convert_kernel<<<(NHTOT + HSQ + 255) / 256, 256>>>(x, lin1_W);
    csr_count<<<EB, 256>>>(ei);
    // launch #4 = profiled slot: lin1 GEMM
    gemm_mma<4, 0><<<GB, 256, SM_TOTAL>>>(Hnb, B1b, bufA, Ab, lin1_b);
    scan1<<<NBK, 256>>>();
    scan2<<<1, 256>>>();
    scan3<<<NBK, 256>>>();
    csr_fill<<<EB, 256>>>(ei);
    readout_kernel<<<GG, HH>>>(bufA, 0);

    float* hcur = bufA;
    float* hnew = bufB;
    for (int i = 0; i < LL; i++) {
        const float* Wi = gnn_W + (size_t)i * 6 * HSQ;
        combine_deg<<<(4 * HSQ + NN + 255) / 256, 256>>>(Wi, naa + i * 4);
        aggregate_kernel<<<WB, 256>>>(hcur);
        gemm_mma<16, 1><<<GB, 256, SM_TOTAL>>>(Ab, Bb, nullptr, Hnb, nullptr);
        gate_kernel<<<WB, 256>>>(hnew, pool_p + (size_t)i * 2 * HH, pa + i * 3);
        readout_kernel<<<GG, HH>>>(hnew, i + 1);
        float* t = hcur; hcur = hnew; hnew = t;
    }

    final_head<<<GG, HH>>>(lin_out_W, lin_out_b, cls_W, cls_b, out);
}

// round 12
// speedup vs baseline: 1.3017x; 1.2146x over previous
#include <cuda_runtime.h>
#include <cuda_fp16.h>
#include <math.h>
#include <cstdint>

#define NN 50000
#define EE 800000
#define GG 512
#define HH 128
#define LL 3
#define OUTC 10
#define NHTOT (NN * HH)
#define HSQ (HH * HH)
#define NB ((NN + 255) / 256)
#define KBIG 512
#define NP 50176
#define NPH (NP * HH)

// ---------------- scratch (device globals) ----------------------------------
__device__ float  d_bufA[NHTOT];
__device__ float  d_bufB[NHTOT];
__device__ float  d_kc[NN];
__device__ float  d_rs[NN];
__device__ float  d_rdeg[NN];
__device__ int    d_rp[NN + 1];
__device__ int    d_cnt[NN];
__device__ int    d_bsum[NB];
__device__ int    d_colsrc[EE];
__device__ float  d_reps[(LL + 1) * GG * HH];
// GEMM A operand: 4 single fp16 planes (0=h, 1=s, 2=sr, 3=g) at c*NPH
__device__ __half d_A[4ULL * NPH];
// GEMM output (and x input): fp16 hi at 0, lo at NPH (22-bit combined)
__device__ __half d_Hn[2ULL * NPH];
__device__ __half d_B[2 * KBIG * HH];   // [n][k] hi plane then lo plane
__device__ __half d_B1[2 * HSQ];        // lin1 W [n][k] hi then lo
__device__ int    d_gs[GG + 1];
__device__ float  d_naa[LL * 4];
__device__ float  d_pa[LL * 3];
__device__ float  d_roa[(LL + 1) * 3];
__device__ float  d_laa[3];
__device__ double d_stats[2];

__device__ __forceinline__ float eluf(float x) { return x > 0.f ? x : expm1f(x); }

__device__ __forceinline__ uint32_t smem_u32(const void* p) {
    uint32_t a;
    asm("{ .reg .u64 t; cvta.to.shared.u64 t, %1; cvt.u32.u64 %0, t; }" : "=r"(a) : "l"(p));
    return a;
}

__device__ __forceinline__ void ldm_x4(uint32_t r[4], uint32_t addr) {
    asm volatile("ldmatrix.sync.aligned.m8n8.x4.shared.b16 {%0,%1,%2,%3}, [%4];"
                 : "=r"(r[0]), "=r"(r[1]), "=r"(r[2]), "=r"(r[3]) : "r"(addr));
}

__device__ __forceinline__ void mma_f16(float c[4], const uint32_t a[4],
                                        uint32_t b0, uint32_t b1) {
    asm volatile(
        "mma.sync.aligned.m16n8k16.row.col.f32.f16.f16.f32 "
        "{%0,%1,%2,%3},{%4,%5,%6,%7},{%8,%9},{%0,%1,%2,%3};"
        : "+f"(c[0]), "+f"(c[1]), "+f"(c[2]), "+f"(c[3])
        : "r"(a[0]), "r"(a[1]), "r"(a[2]), "r"(a[3]), "r"(b0), "r"(b1));
}

#define CP_ASYNC16(dst, src) asm volatile("cp.async.cg.shared.global [%0], [%1], 16;" :: "r"(dst), "l"(src))
#define CP_COMMIT()          asm volatile("cp.async.commit_group;")
#define CP_WAIT(n)           asm volatile("cp.async.wait_group %0;" :: "n"(n))

// 64B-row smem tile (32 fp16/row), XOR swizzle; addr(k0+16) = addr(k0) ^ 32
__device__ __forceinline__ uint32_t swz32(int row, int col) {
    return (uint32_t)(row * 64 + ((((col >> 3) ^ ((row >> 1) & 3))) << 4));
}

// store 4 floats as single fp16 plane
__device__ __forceinline__ void store4h(__half* p, size_t idx, float4 v) {
    *(__half2*)&p[idx]     = __floats2half2_rn(v.x, v.y);
    *(__half2*)&p[idx + 2] = __floats2half2_rn(v.z, v.w);
}

// stage: A(8K) BHI(4K) BLO(4K) = 16KB; 4 stages = 64KB; 3 CTAs = 192KB/SM
#define STG_SZ   16384
#define OFF_BHI  8192
#define OFF_BLO  12288
#define SM_TOTAL 65536

// ---------------- tensor-core GEMM ------------------------------------------
// CTA tile 128(m) x 64(n); warp grid 4m x 2n; warp tile 32x32.
// A: single fp16 plane per chunk (c*NPH). B: split fp16, lo at KB*128.
// Products per k-step: a*bh + a*bl (2 MMAs).
// MODE 0: bias+elu, writes fp32 C + single-plane Csp. MODE 1: elu + LN stats, split Csp.
template <int NSLICES, int MODE>
__global__ void __launch_bounds__(256, 3) gemm_mma(
    const __half* __restrict__ A, const __half* __restrict__ B,
    float* __restrict__ C, __half* __restrict__ Csp,
    const float* __restrict__ bias) {
    extern __shared__ char smem[];
    uint32_t sb = smem_u32(smem);
    const int tid = threadIdx.x;
    const int wid = tid >> 5, lane = tid & 31;
    const int warp_m = wid & 3, warp_n = wid >> 2;
    const int bm = (blockIdx.x >> 1) * 128;
    const int bn = (blockIdx.x & 1) * 64;
    const int KB = NSLICES * 32;
    const int BLO = KB * 128;

    // --- loader mapping: A 128x32 fp16 (8KB), B 64x32 x2 planes (8KB)
    const int lrow = tid >> 1;
    const int lc = (tid & 1) * 16;
    const int brr = tid >> 2;
    const int bcc = (tid & 3) * 8;
    const uint32_t sA0 = swz32(lrow, lc);
    const uint32_t sA1 = swz32(lrow, lc + 8);
    const uint32_t sB  = OFF_BHI + swz32(brr, bcc);
    const __half* Abase = A + (size_t)(bm + lrow) * HH + lc;
    const __half* Bbase = B + (size_t)(bn + brr) * KB + bcc;

    // --- compute mapping
    const int lr = lane & 15, lg2 = (lane >> 4) * 8;
    const int m_base = warp_m * 32;
    const int n_base = warp_n * 32;
    uint32_t aoff[2], boff[2];
#pragma unroll
    for (int mt = 0; mt < 2; mt++) aoff[mt] = swz32(m_base + mt * 16 + lr, lg2);
#pragma unroll
    for (int np = 0; np < 2; np++) boff[np] = OFF_BHI + swz32(n_base + np * 16 + lr, lg2);

    float acc[2][4][4];
#pragma unroll
    for (int i = 0; i < 2; i++)
#pragma unroll
        for (int j = 0; j < 4; j++)
#pragma unroll
            for (int q = 0; q < 4; q++) acc[i][j][q] = 0.f;

    // prologue: prefetch slices 0..2
#pragma unroll
    for (int pf = 0; pf < 3 && pf < NSLICES; pf++) {
        const __half* ap = Abase + (size_t)(pf >> 2) * NPH + (pf & 3) * 32;
        const __half* bp = Bbase + pf * 32;
        uint32_t base = sb + pf * STG_SZ;
        CP_ASYNC16(base + sA0, ap);
        CP_ASYNC16(base + sA1, ap + 8);
        CP_ASYNC16(base + sB, bp);
        CP_ASYNC16(base + sB + (OFF_BLO - OFF_BHI), bp + BLO);
        CP_COMMIT();
    }

#pragma unroll
    for (int s = 0; s < NSLICES; s++) {
        // committed so far = min(s+3, NSLICES); need group s done
        if (s + 3 <= NSLICES) { CP_WAIT(2); }
        else if (s + 2 == NSLICES) { CP_WAIT(1); }
        else { CP_WAIT(0); }
        __syncthreads();
        if (s + 3 < NSLICES) {
            const int sn = s + 3;
            const __half* ap = Abase + (size_t)(sn >> 2) * NPH + (sn & 3) * 32;
            const __half* bp = Bbase + sn * 32;
            uint32_t base = sb + (sn & 3) * STG_SZ;
            CP_ASYNC16(base + sA0, ap);
            CP_ASYNC16(base + sA1, ap + 8);
            CP_ASYNC16(base + sB, bp);
            CP_ASYNC16(base + sB + (OFF_BLO - OFF_BHI), bp + BLO);
            CP_COMMIT();
        }
        const uint32_t sbase = sb + (uint32_t)((s & 3) * STG_SZ);
#pragma unroll
        for (int ks = 0; ks < 2; ks++) {
            const uint32_t kx = ks * 32;
            uint32_t bhm[2][4], blm[2][4];
#pragma unroll
            for (int np = 0; np < 2; np++) {
                uint32_t ad = sbase + (boff[np] ^ kx);
                ldm_x4(bhm[np], ad);
                ldm_x4(blm[np], ad + (OFF_BLO - OFF_BHI));
            }
#pragma unroll
            for (int mt = 0; mt < 2; mt++) {
                uint32_t a[4];
                ldm_x4(a, sbase + (aoff[mt] ^ kx));
#pragma unroll
                for (int nt = 0; nt < 4; nt++) {
                    int np = nt >> 1, sel = nt & 1;
                    uint32_t b0h = sel ? bhm[np][1] : bhm[np][0];
                    uint32_t b1h = sel ? bhm[np][3] : bhm[np][2];
                    uint32_t b0l = sel ? blm[np][1] : blm[np][0];
                    uint32_t b1l = sel ? blm[np][3] : blm[np][2];
                    mma_f16(acc[mt][nt], a, b0h, b1h);
                    mma_f16(acc[mt][nt], a, b0l, b1l);
                }
            }
        }
    }
    __syncthreads();

    // ---- epilogue
    float lsum = 0.f, lsq = 0.f;
    int rq = lane >> 2, cq = (lane & 3) * 2;
#pragma unroll
    for (int mt = 0; mt < 2; mt++) {
#pragma unroll
        for (int half = 0; half < 2; half++) {
            int gm = bm + m_base + mt * 16 + rq + half * 8;
            if (gm >= NN) continue;
#pragma unroll
            for (int nt = 0; nt < 4; nt++) {
                int col = bn + n_base + nt * 8 + cq;
                float v0 = acc[mt][nt][half * 2];
                float v1 = acc[mt][nt][half * 2 + 1];
                size_t ci = (size_t)gm * HH + col;
                if (MODE == 0) {
                    v0 = eluf(v0 + bias[col]);
                    v1 = eluf(v1 + bias[col + 1]);
                    *(float2*)&C[ci] = make_float2(v0, v1);
                    *(__half2*)&Csp[ci] = __floats2half2_rn(v0, v1);
                } else {
                    v0 = eluf(v0); v1 = eluf(v1);
                    lsum += v0 + v1;
                    lsq = fmaf(v0, v0, lsq); lsq = fmaf(v1, v1, lsq);
                    __half2 h = __floats2half2_rn(v0, v1);
                    float2 hf = __half22float2(h);
                    *(__half2*)&Csp[ci] = h;
                    *(__half2*)&Csp[NPH + ci] = __floats2half2_rn(v0 - hf.x, v1 - hf.y);
                }
            }
        }
    }
    if (MODE == 1) {
        double ds = (double)lsum, dq = (double)lsq;
#pragma unroll
        for (int o = 16; o; o >>= 1) {
            ds += __shfl_down_sync(0xffffffffu, ds, o);
            dq += __shfl_down_sync(0xffffffffu, dq, o);
        }
        __shared__ double ssum[8], ssq[8];
        if (lane == 0) { ssum[wid] = ds; ssq[wid] = dq; }
        __syncthreads();
        if (tid == 0) {
            double a = 0.0, b = 0.0;
#pragma unroll
            for (int i = 0; i < 8; i++) { a += ssum[i]; b += ssq[i]; }
            atomicAdd(&d_stats[0], a);
            atomicAdd(&d_stats[1], b);
        }
    }
}

// ---------------- setup ------------------------------------------------------
__device__ void softmax_n(const float* in, float* out, int n) {
    float m = in[0];
    for (int i = 1; i < n; i++) m = fmaxf(m, in[i]);
    float s = 0.f;
    for (int i = 0; i < n; i++) { out[i] = expf(in[i] - m); s += out[i]; }
    float inv = 1.f / s;
    for (int i = 0; i < n; i++) out[i] *= inv;
}

__global__ void setup_kernel(const int* __restrict__ batch,
                             const float* __restrict__ na, const float* __restrict__ pl,
                             const float* __restrict__ ro, const float* __restrict__ la) {
    int i = blockIdx.x * blockDim.x + threadIdx.x;
    if (i <= GG) {
        int lo = 0, hi = NN;
        while (lo < hi) { int mid = (lo + hi) >> 1; if (batch[mid] < i) lo = mid + 1; else hi = mid; }
        d_gs[i] = lo;
    }
    if (i < NN) { d_kc[i] = 1.f; d_cnt[i] = 0; }
    if (i == 0) {
        for (int l = 0; l < LL; l++) softmax_n(na + l * 4, d_naa + l * 4, 4);
        for (int l = 0; l < LL; l++) softmax_n(pl + l * 3, d_pa + l * 3, 3);
        for (int l = 0; l < LL + 1; l++) softmax_n(ro + l * 3, d_roa + l * 3, 3);
        softmax_n(la, d_laa, 3);
    }
}

// x -> d_Hn plane0 (single fp16); lin1 W -> d_B1 [n][k] split fp16
__global__ void convert_kernel(const float* __restrict__ x, const float* __restrict__ W) {
    int idx = blockIdx.x * blockDim.x + threadIdx.x;
    if (idx < NHTOT) {
        d_Hn[idx] = __float2half(x[idx]);
    } else if (idx < NHTOT + HSQ) {
        int i = idx - NHTOT;
        int k = i >> 7, n = i & 127;
        float v = W[k * HH + n];
        __half h = __float2half(v);
        d_B1[n * HH + k] = h;
        d_B1[HSQ + n * HH + k] = __float2half(v - __half2float(h));
    }
}

__global__ void csr_count(const int* __restrict__ ei) {
    int e = blockIdx.x * blockDim.x + threadIdx.x;
    if (e >= EE) return;
    atomicAdd(&d_cnt[ei[EE + e]], 1);
}

__global__ void scan1() {
    __shared__ int sh[256];
    int i = blockIdx.x * 256 + threadIdx.x;
    int v = (i < NN) ? d_cnt[i] : 0;
    sh[threadIdx.x] = v;
    __syncthreads();
#pragma unroll
    for (int d = 1; d < 256; d <<= 1) {
        int t = (threadIdx.x >= d) ? sh[threadIdx.x - d] : 0;
        __syncthreads();
        sh[threadIdx.x] += t;
        __syncthreads();
    }
    if (i < NN) d_rp[i + 1] = sh[threadIdx.x];
    if (threadIdx.x == 255) d_bsum[blockIdx.x] = sh[255];
}

__global__ void scan2() {
    __shared__ int sh[256];
    int t = threadIdx.x;
    int v = (t < NB) ? d_bsum[t] : 0;
    sh[t] = v;
    __syncthreads();
#pragma unroll
    for (int d = 1; d < 256; d <<= 1) {
        int tv = (t >= d) ? sh[t - d] : 0;
        __syncthreads();
        sh[t] += tv;
        __syncthreads();
    }
    if (t < NB) d_bsum[t] = sh[t] - v;
}

__global__ void scan3() {
    int i = blockIdx.x * 256 + threadIdx.x;
    if (i < NN) d_rp[i + 1] += d_bsum[blockIdx.x];
    if (i == 0) d_rp[0] = 0;
}

__global__ void csr_fill(const int* __restrict__ ei) {
    int e = blockIdx.x * blockDim.x + threadIdx.x;
    if (e >= EE) return;
    int d = ei[EE + e];
    int old = atomicSub(&d_cnt[d], 1);
    d_colsrc[d_rp[d] + old - 1] = ei[e];
}

// combine_W + deg + stats zero
__global__ void combine_deg(const float* __restrict__ W, const float* __restrict__ na) {
    int idx = blockIdx.x * blockDim.x + threadIdx.x;
    if (idx == 0) { d_stats[0] = 0.0; d_stats[1] = 0.0; }
    if (idx < 4 * HSQ) {
        int k = idx >> 7, n = idx & 127;
        int p = k >> 7, kk = k & 127;
        int widx = kk * HH + n;
        float a0 = na[0], a1 = na[1], a2 = na[2], a3 = na[3];
        float v;
        if (p == 0)      v = a1 * W[2 * HSQ + widx] + a2 * W[3 * HSQ + widx] + a3 * W[4 * HSQ + widx];
        else if (p == 1) v = a2 * W[3 * HSQ + widx] + a3 * W[5 * HSQ + widx];
        else if (p == 2) v = a1 * W[1 * HSQ + widx];
        else             v = a0 * W[widx];
        __half h = __float2half(v);
        d_B[(size_t)n * KBIG + k] = h;
        d_B[KBIG * HH + (size_t)n * KBIG + k] = __float2half(v - __half2float(h));
    } else {
        int n = idx - 4 * HSQ;
        if (n < NN) {
            float kcn = d_kc[n];
            float s = kcn;
            int b = d_rp[n], e = d_rp[n + 1];
            for (int p = b; p < e; p++) s += d_kc[d_colsrc[p]];
            float dg = fmaxf(kcn * s, 1e-6f);
            d_rdeg[n] = 1.f / dg;
            d_rs[n] = rsqrtf(dg);
        }
    }
}

// ---------------- gather aggregation (writes single fp16 planes) ------------
__global__ void aggregate_kernel(const float* __restrict__ h) {
    int gw = (blockIdx.x * blockDim.x + threadIdx.x) >> 5;
    int lane = threadIdx.x & 31;
    if (gw >= NN) return;
    float kcd = d_kc[gw];
    float rsd = d_rs[gw];
    float rdg = d_rdeg[gw];
    const float4* h4 = (const float4*)h;
    float4 hv = h4[(size_t)gw * 32 + lane];
    float wg = kcd * rsd;
    float4 as = {hv.x * kcd, hv.y * kcd, hv.z * kcd, hv.w * kcd};
    float4 ag = {hv.x * wg, hv.y * wg, hv.z * wg, hv.w * wg};
    int beg = d_rp[gw], end = d_rp[gw + 1];
    for (int p = beg; p < end; p++) {
        int s = d_colsrc[p];
        float w1 = d_kc[s];
        if (w1 != 0.f) {
            float rv = d_rs[s];
            float4 hs = h4[(size_t)s * 32 + lane];
            as.x += hs.x; as.y += hs.y; as.z += hs.z; as.w += hs.w;
            ag.x = fmaf(hs.x, rv, ag.x); ag.y = fmaf(hs.y, rv, ag.y);
            ag.z = fmaf(hs.z, rv, ag.z); ag.w = fmaf(hs.w, rv, ag.w);
        }
    }
    float fg = kcd * rsd;
    as.x *= kcd; as.y *= kcd; as.z *= kcd; as.w *= kcd;
    ag.x *= fg;  ag.y *= fg;  ag.z *= fg;  ag.w *= fg;
    float4 asr = {as.x * rdg, as.y * rdg, as.z * rdg, as.w * rdg};
    size_t idx = (size_t)gw * HH + lane * 4;
    store4h(d_A + 1ULL * NPH, idx, as);
    store4h(d_A + 2ULL * NPH, idx, asr);
    store4h(d_A + 3ULL * NPH, idx, ag);
}

// ---------------- layernorm + gate + pool (reads d_Hn split fp16) -----------
__global__ void gate_kernel(float* __restrict__ h, const float* __restrict__ p0,
                            const float* __restrict__ pa) {
    int gw = (blockIdx.x * blockDim.x + threadIdx.x) >> 5;
    int lane = threadIdx.x & 31;
    if (gw >= NN) return;
    const double invc = 1.0 / ((double)NN * (double)HH);
    double md = d_stats[0] * invc;
    double vd = d_stats[1] * invc - md * md;
    float mean = (float)md;
    float inv = rsqrtf((float)vd + 1e-5f);
    size_t idx = (size_t)gw * HH + lane * 4;
    float2 fh0 = __half22float2(*(const __half2*)&d_Hn[idx]);
    float2 fh1 = __half22float2(*(const __half2*)&d_Hn[idx + 2]);
    float2 fl0 = __half22float2(*(const __half2*)&d_Hn[NPH + idx]);
    float2 fl1 = __half22float2(*(const __half2*)&d_Hn[NPH + idx + 2]);
    float4 hv = {fh0.x + fl0.x, fh0.y + fl0.y, fh1.x + fl1.x, fh1.y + fl1.y};
    float4 hn;
    hn.x = (hv.x - mean) * inv; hn.y = (hv.y - mean) * inv;
    hn.z = (hv.z - mean) * inv; hn.w = (hv.w - mean) * inv;
    float4 a = ((const float4*)p0)[lane];
    float4 b = ((const float4*)(p0 + HH))[lane];
    float d0 = hn.x * a.x + hn.y * a.y + hn.z * a.z + hn.w * a.w;
    float d1 = hn.x * b.x + hn.y * b.y + hn.z * b.z + hn.w * b.w;
#pragma unroll
    for (int o = 16; o; o >>= 1) {
        d0 += __shfl_xor_sync(0xffffffffu, d0, o);
        d1 += __shfl_xor_sync(0xffffffffu, d1, o);
    }
    float g1 = 1.f / (1.f + expf(-d0));
    float g2 = tanhf(d1);
    float gate = pa[0] * g1 + pa[1] * g2 + pa[2];
    float kv = gate > 0.01f ? 1.f : 0.f;
    float sc = gate * kv;
    hn.x *= sc; hn.y *= sc; hn.z *= sc; hn.w *= sc;
    ((float4*)h)[(size_t)gw * 32 + lane] = hn;
    store4h(d_A, idx, hn);
    if (lane == 0) d_kc[gw] *= kv;
}

// ---------------- readout ----------------------------------------------------
__global__ void readout_kernel(const float* __restrict__ h, int r) {
    int g = blockIdx.x, k = threadIdx.x;
    int b = d_gs[g], e = d_gs[g + 1];
    float s = 0.f, mx = -INFINITY;
    for (int n = b; n < e; n++) {
        float v = h[(size_t)n * HH + k];
        s += v;
        mx = fmaxf(mx, v);
    }
    float c = (float)(e - b);
    float mean = s / fmaxf(c, 1.f);
    if (e == b) mx = 0.f;
    const float* w = d_roa + r * 3;
    d_reps[((size_t)r * GG + g) * HH + k] = w[0] * mean + w[1] * mx + w[2] * s;
}

// ---------------- final head -------------------------------------------------
__global__ void final_head(const float* __restrict__ Wo, const float* __restrict__ bo,
                           const float* __restrict__ Wc, const float* __restrict__ bc,
                           float* __restrict__ out) {
    __shared__ float zr[HH];
    __shared__ float z2[HH];
    __shared__ float lg[OUTC];
    __shared__ float s_lse;
    int g = blockIdx.x, k = threadIdx.x;
    int idx = g * HH + k;
    float r0 = d_reps[idx];
    float r1 = d_reps[GG * HH + idx];
    float r2 = d_reps[2 * GG * HH + idx];
    float r3 = d_reps[3 * GG * HH + idx];
    float s = r0 + r1 + r2 + r3;
    float mx = fmaxf(fmaxf(r0, r1), fmaxf(r2, r3));
    zr[k] = d_laa[0] * eluf(s) + d_laa[1] * eluf(s * 0.25f) + d_laa[2] * eluf(mx);
    __syncthreads();
    float acc = bo[k];
    for (int k2 = 0; k2 < HH; k2++) acc = fmaf(zr[k2], Wo[k2 * HH + k], acc);
    z2[k] = eluf(acc);
    __syncthreads();
    if (k < OUTC) {
        float accl = bc[k];
        for (int k2 = 0; k2 < HH; k2++) accl = fmaf(z2[k2], Wc[k2 * OUTC + k], accl);
        lg[k] = accl;
    }
    __syncthreads();
    if (k == 0) {
        float m = lg[0];
        for (int i = 1; i < OUTC; i++) m = fmaxf(m, lg[i]);
        float se = 0.f;
        for (int i = 0; i < OUTC; i++) se += expf(lg[i] - m);
        s_lse = m + logf(se);
    }
    __syncthreads();
    if (k < OUTC) out[g * OUTC + k] = lg[k] - s_lse;
}

// ---------------- launch ------------------------------------------------------
extern "C" void kernel_launch(void* const* d_in, const int* in_sizes, int n_in,
                              void* d_out, int out_size) {
    const float* x         = (const float*)d_in[0];
    const int*   ei        = (const int*)d_in[1];
    const int*   batch     = (const int*)d_in[2];
    const float* lin1_W    = (const float*)d_in[3];
    const float* lin1_b    = (const float*)d_in[4];
    const float* gnn_W     = (const float*)d_in[5];
    const float* pool_p    = (const float*)d_in[6];
    const float* lin_out_W = (const float*)d_in[7];
    const float* lin_out_b = (const float*)d_in[8];
    const float* cls_W     = (const float*)d_in[9];
    const float* cls_b     = (const float*)d_in[10];
    const float* na_log    = (const float*)d_in[11];
    const float* pool_log  = (const float*)d_in[12];
    const float* ro_log    = (const float*)d_in[13];
    const float* la_log    = (const float*)d_in[14];
    float* out = (float*)d_out;

    float *bufA, *bufB, *naa, *pa;
    __half *Ab, *Hnb, *Bb, *B1b;
    cudaGetSymbolAddress((void**)&bufA, d_bufA);
    cudaGetSymbolAddress((void**)&bufB, d_bufB);
    cudaGetSymbolAddress((void**)&naa, d_naa);
    cudaGetSymbolAddress((void**)&pa, d_pa);
    cudaGetSymbolAddress((void**)&Ab, d_A);
    cudaGetSymbolAddress((void**)&Hnb, d_Hn);
    cudaGetSymbolAddress((void**)&Bb, d_B);
    cudaGetSymbolAddress((void**)&B1b, d_B1);

    cudaFuncSetAttribute(gemm_mma<4, 0>, cudaFuncAttributeMaxDynamicSharedMemorySize, SM_TOTAL);
    cudaFuncSetAttribute(gemm_mma<16, 1>, cudaFuncAttributeMaxDynamicSharedMemorySize, SM_TOTAL);

    const int GB = ((NN + 127) / 128) * 2;   // 782
    const int EB = (EE + 255) / 256;
    const int WB = (NN * 32 + 255) / 256;
    const int NBK = (NN + 255) / 256;

    setup_kernel<<<NBK, 256>>>(batch, na_log, pool_log, ro_log, la_log);
    convert_kernel<<<(NHTOT + HSQ + 255) / 256, 256>>>(x, lin1_W);
    csr_count<<<EB, 256>>>(ei);
    // launch #4 = profiled slot: lin1 GEMM (A = fp16(x) in d_Hn plane0)
    gemm_mma<4, 0><<<GB, 256, SM_TOTAL>>>(Hnb, B1b, bufA, Ab, lin1_b);
    scan1<<<NBK, 256>>>();
    scan2<<<1, 256>>>();
    scan3<<<NBK, 256>>>();
    csr_fill<<<EB, 256>>>(ei);
    readout_kernel<<<GG, HH>>>(bufA, 0);

    float* hcur = bufA;
    float* hnew = bufB;
    for (int i = 0; i < LL; i++) {
        const float* Wi = gnn_W + (size_t)i * 6 * HSQ;
        combine_deg<<<(4 * HSQ + NN + 255) / 256, 256>>>(Wi, naa + i * 4);
        aggregate_kernel<<<WB, 256>>>(hcur);
        gemm_mma<16, 1><<<GB, 256, SM_TOTAL>>>(Ab, Bb, nullptr, Hnb, nullptr);
        gate_kernel<<<WB, 256>>>(hnew, pool_p + (size_t)i * 2 * HH, pa + i * 3);
        readout_kernel<<<GG, HH>>>(hnew, i + 1);
        float* t = hcur; hcur = hnew; hnew = t;
    }

    final_head<<<GG, HH>>>(lin_out_W, lin_out_b, cls_W, cls_b, out);
}

// round 13
// speedup vs baseline: 1.4369x; 1.1039x over previous
#include <cuda_runtime.h>
#include <cuda_fp16.h>
#include <math.h>
#include <cstdint>

#define NN 50000
#define EE 800000
#define GG 512
#define HH 128
#define LL 3
#define OUTC 10
#define NHTOT (NN * HH)
#define HSQ (HH * HH)
#define NB ((NN + 255) / 256)
#define KBIG 512
#define NP 50176
#define NPH (NP * HH)

// ---------------- scratch (device globals) ----------------------------------
__device__ float  d_bufA[NHTOT];
__device__ float  d_bufB[NHTOT];
__device__ float  d_kc[NN];
__device__ float  d_rs[NN];
__device__ float  d_rdeg[NN];
__device__ int    d_rp[NN + 1];
__device__ int    d_cnt[NN];
__device__ int    d_bsum[NB];
__device__ int    d_colsrc[EE];
__device__ float  d_reps[(LL + 1) * GG * HH];
// GEMM A operand: 4 single fp16 planes (0=h, 1=s, 2=sr, 3=g) at c*NPH
__device__ __half d_A[4ULL * NPH];
// GEMM output (and x input): fp16 hi at 0, lo at NPH (22-bit combined for LN path)
__device__ __half d_Hn[2ULL * NPH];
__device__ __half d_B[KBIG * HH];   // combined B [n][k], single fp16
__device__ __half d_B1[HSQ];        // lin1 W [n][k], single fp16
__device__ int    d_gs[GG + 1];
__device__ float  d_naa[LL * 4];
__device__ float  d_pa[LL * 3];
__device__ float  d_roa[(LL + 1) * 3];
__device__ float  d_laa[3];
__device__ double d_stats[2];

__device__ __forceinline__ float eluf(float x) { return x > 0.f ? x : expm1f(x); }

__device__ __forceinline__ uint32_t smem_u32(const void* p) {
    uint32_t a;
    asm("{ .reg .u64 t; cvta.to.shared.u64 t, %1; cvt.u32.u64 %0, t; }" : "=r"(a) : "l"(p));
    return a;
}

__device__ __forceinline__ void ldm_x4(uint32_t r[4], uint32_t addr) {
    asm volatile("ldmatrix.sync.aligned.m8n8.x4.shared.b16 {%0,%1,%2,%3}, [%4];"
                 : "=r"(r[0]), "=r"(r[1]), "=r"(r[2]), "=r"(r[3]) : "r"(addr));
}

__device__ __forceinline__ void mma_f16(float c[4], const uint32_t a[4],
                                        uint32_t b0, uint32_t b1) {
    asm volatile(
        "mma.sync.aligned.m16n8k16.row.col.f32.f16.f16.f32 "
        "{%0,%1,%2,%3},{%4,%5,%6,%7},{%8,%9},{%0,%1,%2,%3};"
        : "+f"(c[0]), "+f"(c[1]), "+f"(c[2]), "+f"(c[3])
        : "r"(a[0]), "r"(a[1]), "r"(a[2]), "r"(a[3]), "r"(b0), "r"(b1));
}

#define CP_ASYNC16(dst, src) asm volatile("cp.async.cg.shared.global [%0], [%1], 16;" :: "r"(dst), "l"(src))
#define CP_COMMIT()          asm volatile("cp.async.commit_group;")
#define CP_WAIT(n)           asm volatile("cp.async.wait_group %0;" :: "n"(n))

// 64B-row smem tile (32 fp16/row), XOR swizzle; addr(k0+16) = addr(k0) ^ 32
__device__ __forceinline__ uint32_t swz32(int row, int col) {
    return (uint32_t)(row * 64 + ((((col >> 3) ^ ((row >> 1) & 3))) << 4));
}

__device__ __forceinline__ void store4h(__half* p, size_t idx, float4 v) {
    *(__half2*)&p[idx]     = __floats2half2_rn(v.x, v.y);
    *(__half2*)&p[idx + 2] = __floats2half2_rn(v.z, v.w);
}

// stage: A(8K) B(4K) = 12KB; 4 stages = 48KB; 4 CTAs = 192KB/SM
#define STG_SZ   12288
#define OFF_B    8192
#define SM_TOTAL 49152

// ---------------- tensor-core GEMM ------------------------------------------
// CTA tile 128(m) x 64(n); warp grid 4m x 2n; warp tile 32x32.
// A: single fp16 plane per chunk (c*NPH). B: single fp16 [n][k].
// 1 MMA per (mt,nt,k-step).
// MODE 0: bias+elu, fp32 C + single-plane Csp. MODE 1: elu + LN stats, split Csp.
template <int NSLICES, int MODE>
__global__ void __launch_bounds__(256, 4) gemm_mma(
    const __half* __restrict__ A, const __half* __restrict__ B,
    float* __restrict__ C, __half* __restrict__ Csp,
    const float* __restrict__ bias) {
    extern __shared__ char smem[];
    uint32_t sb = smem_u32(smem);
    const int tid = threadIdx.x;
    const int wid = tid >> 5, lane = tid & 31;
    const int warp_m = wid & 3, warp_n = wid >> 2;
    const int bm = (blockIdx.x >> 1) * 128;
    const int bn = (blockIdx.x & 1) * 64;
    const int KB = NSLICES * 32;

    // --- loader mapping: A 128x32 fp16 (8KB, 2x16B/thread), B 64x32 (4KB, 1x16B/thread)
    const int lrow = tid >> 1;
    const int lc = (tid & 1) * 16;
    const int brr = tid >> 2;
    const int bcc = (tid & 3) * 8;
    const uint32_t sA0 = swz32(lrow, lc);
    const uint32_t sA1 = swz32(lrow, lc + 8);
    const uint32_t sB  = OFF_B + swz32(brr, bcc);
    const __half* Abase = A + (size_t)(bm + lrow) * HH + lc;
    const __half* Bbase = B + (size_t)(bn + brr) * KB + bcc;

    // --- compute mapping
    const int lr = lane & 15, lg2 = (lane >> 4) * 8;
    const int m_base = warp_m * 32;
    const int n_base = warp_n * 32;
    uint32_t aoff[2], boff[2];
#pragma unroll
    for (int mt = 0; mt < 2; mt++) aoff[mt] = swz32(m_base + mt * 16 + lr, lg2);
#pragma unroll
    for (int np = 0; np < 2; np++) boff[np] = OFF_B + swz32(n_base + np * 16 + lr, lg2);

    float acc[2][4][4];
#pragma unroll
    for (int i = 0; i < 2; i++)
#pragma unroll
        for (int j = 0; j < 4; j++)
#pragma unroll
            for (int q = 0; q < 4; q++) acc[i][j][q] = 0.f;

    // prologue: prefetch slices 0..2
#pragma unroll
    for (int pf = 0; pf < 3 && pf < NSLICES; pf++) {
        const __half* ap = Abase + (size_t)(pf >> 2) * NPH + (pf & 3) * 32;
        const __half* bp = Bbase + pf * 32;
        uint32_t base = sb + pf * STG_SZ;
        CP_ASYNC16(base + sA0, ap);
        CP_ASYNC16(base + sA1, ap + 8);
        CP_ASYNC16(base + sB, bp);
        CP_COMMIT();
    }

#pragma unroll
    for (int s = 0; s < NSLICES; s++) {
        if (s + 3 <= NSLICES) { CP_WAIT(2); }
        else if (s + 2 == NSLICES) { CP_WAIT(1); }
        else { CP_WAIT(0); }
        __syncthreads();
        if (s + 3 < NSLICES) {
            const int sn = s + 3;
            const __half* ap = Abase + (size_t)(sn >> 2) * NPH + (sn & 3) * 32;
            const __half* bp = Bbase + sn * 32;
            uint32_t base = sb + (sn & 3) * STG_SZ;
            CP_ASYNC16(base + sA0, ap);
            CP_ASYNC16(base + sA1, ap + 8);
            CP_ASYNC16(base + sB, bp);
            CP_COMMIT();
        }
        const uint32_t sbase = sb + (uint32_t)((s & 3) * STG_SZ);
#pragma unroll
        for (int ks = 0; ks < 2; ks++) {
            const uint32_t kx = ks * 32;
            uint32_t bmr[2][4];
#pragma unroll
            for (int np = 0; np < 2; np++)
                ldm_x4(bmr[np], sbase + (boff[np] ^ kx));
#pragma unroll
            for (int mt = 0; mt < 2; mt++) {
                uint32_t a[4];
                ldm_x4(a, sbase + (aoff[mt] ^ kx));
#pragma unroll
                for (int nt = 0; nt < 4; nt++) {
                    int np = nt >> 1, sel = nt & 1;
                    uint32_t b0 = sel ? bmr[np][1] : bmr[np][0];
                    uint32_t b1 = sel ? bmr[np][3] : bmr[np][2];
                    mma_f16(acc[mt][nt], a, b0, b1);
                }
            }
        }
    }
    __syncthreads();

    // ---- epilogue
    float lsum = 0.f, lsq = 0.f;
    int rq = lane >> 2, cq = (lane & 3) * 2;
#pragma unroll
    for (int mt = 0; mt < 2; mt++) {
#pragma unroll
        for (int half = 0; half < 2; half++) {
            int gm = bm + m_base + mt * 16 + rq + half * 8;
            if (gm >= NN) continue;
#pragma unroll
            for (int nt = 0; nt < 4; nt++) {
                int col = bn + n_base + nt * 8 + cq;
                float v0 = acc[mt][nt][half * 2];
                float v1 = acc[mt][nt][half * 2 + 1];
                size_t ci = (size_t)gm * HH + col;
                if (MODE == 0) {
                    v0 = eluf(v0 + bias[col]);
                    v1 = eluf(v1 + bias[col + 1]);
                    *(float2*)&C[ci] = make_float2(v0, v1);
                    *(__half2*)&Csp[ci] = __floats2half2_rn(v0, v1);
                } else {
                    v0 = eluf(v0); v1 = eluf(v1);
                    lsum += v0 + v1;
                    lsq = fmaf(v0, v0, lsq); lsq = fmaf(v1, v1, lsq);
                    __half2 h = __floats2half2_rn(v0, v1);
                    float2 hf = __half22float2(h);
                    *(__half2*)&Csp[ci] = h;
                    *(__half2*)&Csp[NPH + ci] = __floats2half2_rn(v0 - hf.x, v1 - hf.y);
                }
            }
        }
    }
    if (MODE == 1) {
        double ds = (double)lsum, dq = (double)lsq;
#pragma unroll
        for (int o = 16; o; o >>= 1) {
            ds += __shfl_down_sync(0xffffffffu, ds, o);
            dq += __shfl_down_sync(0xffffffffu, dq, o);
        }
        __shared__ double ssum[8], ssq[8];
        if (lane == 0) { ssum[wid] = ds; ssq[wid] = dq; }
        __syncthreads();
        if (tid == 0) {
            double a = 0.0, b = 0.0;
#pragma unroll
            for (int i = 0; i < 8; i++) { a += ssum[i]; b += ssq[i]; }
            atomicAdd(&d_stats[0], a);
            atomicAdd(&d_stats[1], b);
        }
    }
}

// ---------------- setup ------------------------------------------------------
__device__ void softmax_n(const float* in, float* out, int n) {
    float m = in[0];
    for (int i = 1; i < n; i++) m = fmaxf(m, in[i]);
    float s = 0.f;
    for (int i = 0; i < n; i++) { out[i] = expf(in[i] - m); s += out[i]; }
    float inv = 1.f / s;
    for (int i = 0; i < n; i++) out[i] *= inv;
}

__global__ void setup_kernel(const int* __restrict__ batch,
                             const float* __restrict__ na, const float* __restrict__ pl,
                             const float* __restrict__ ro, const float* __restrict__ la) {
    int i = blockIdx.x * blockDim.x + threadIdx.x;
    if (i <= GG) {
        int lo = 0, hi = NN;
        while (lo < hi) { int mid = (lo + hi) >> 1; if (batch[mid] < i) lo = mid + 1; else hi = mid; }
        d_gs[i] = lo;
    }
    if (i < NN) { d_kc[i] = 1.f; d_cnt[i] = 0; }
    if (i == 0) {
        for (int l = 0; l < LL; l++) softmax_n(na + l * 4, d_naa + l * 4, 4);
        for (int l = 0; l < LL; l++) softmax_n(pl + l * 3, d_pa + l * 3, 3);
        for (int l = 0; l < LL + 1; l++) softmax_n(ro + l * 3, d_roa + l * 3, 3);
        softmax_n(la, d_laa, 3);
    }
}

// x -> d_Hn plane0 (single fp16); lin1 W -> d_B1 [n][k] single fp16
__global__ void convert_kernel(const float* __restrict__ x, const float* __restrict__ W) {
    int idx = blockIdx.x * blockDim.x + threadIdx.x;
    if (idx < NHTOT) {
        d_Hn[idx] = __float2half(x[idx]);
    } else if (idx < NHTOT + HSQ) {
        int i = idx - NHTOT;
        int k = i >> 7, n = i & 127;
        d_B1[n * HH + k] = __float2half(W[k * HH + n]);
    }
}

__global__ void csr_count(const int* __restrict__ ei) {
    int e = blockIdx.x * blockDim.x + threadIdx.x;
    if (e >= EE) return;
    atomicAdd(&d_cnt[ei[EE + e]], 1);
}

__global__ void scan1() {
    __shared__ int sh[256];
    int i = blockIdx.x * 256 + threadIdx.x;
    int v = (i < NN) ? d_cnt[i] : 0;
    sh[threadIdx.x] = v;
    __syncthreads();
#pragma unroll
    for (int d = 1; d < 256; d <<= 1) {
        int t = (threadIdx.x >= d) ? sh[threadIdx.x - d] : 0;
        __syncthreads();
        sh[threadIdx.x] += t;
        __syncthreads();
    }
    if (i < NN) d_rp[i + 1] = sh[threadIdx.x];
    if (threadIdx.x == 255) d_bsum[blockIdx.x] = sh[255];
}

__global__ void scan2() {
    __shared__ int sh[256];
    int t = threadIdx.x;
    int v = (t < NB) ? d_bsum[t] : 0;
    sh[t] = v;
    __syncthreads();
#pragma unroll
    for (int d = 1; d < 256; d <<= 1) {
        int tv = (t >= d) ? sh[t - d] : 0;
        __syncthreads();
        sh[t] += tv;
        __syncthreads();
    }
    if (t < NB) d_bsum[t] = sh[t] - v;
}

__global__ void scan3() {
    int i = blockIdx.x * 256 + threadIdx.x;
    if (i < NN) d_rp[i + 1] += d_bsum[blockIdx.x];
    if (i == 0) d_rp[0] = 0;
}

__global__ void csr_fill(const int* __restrict__ ei) {
    int e = blockIdx.x * blockDim.x + threadIdx.x;
    if (e >= EE) return;
    int d = ei[EE + e];
    int old = atomicSub(&d_cnt[d], 1);
    d_colsrc[d_rp[d] + old - 1] = ei[e];
}

// combine_W + deg + stats zero
__global__ void combine_deg(const float* __restrict__ W, const float* __restrict__ na) {
    int idx = blockIdx.x * blockDim.x + threadIdx.x;
    if (idx == 0) { d_stats[0] = 0.0; d_stats[1] = 0.0; }
    if (idx < 4 * HSQ) {
        int k = idx >> 7, n = idx & 127;
        int p = k >> 7, kk = k & 127;
        int widx = kk * HH + n;
        float a0 = na[0], a1 = na[1], a2 = na[2], a3 = na[3];
        float v;
        if (p == 0)      v = a1 * W[2 * HSQ + widx] + a2 * W[3 * HSQ + widx] + a3 * W[4 * HSQ + widx];
        else if (p == 1) v = a2 * W[3 * HSQ + widx] + a3 * W[5 * HSQ + widx];
        else if (p == 2) v = a1 * W[1 * HSQ + widx];
        else             v = a0 * W[widx];
        d_B[(size_t)n * KBIG + k] = __float2half(v);
    } else {
        int n = idx - 4 * HSQ;
        if (n < NN) {
            float kcn = d_kc[n];
            float s = kcn;
            int b = d_rp[n], e = d_rp[n + 1];
            for (int p = b; p < e; p++) s += d_kc[d_colsrc[p]];
            float dg = fmaxf(kcn * s, 1e-6f);
            d_rdeg[n] = 1.f / dg;
            d_rs[n] = rsqrtf(dg);
        }
    }
}

// ---------------- gather aggregation (writes single fp16 planes) ------------
__global__ void aggregate_kernel(const float* __restrict__ h) {
    int gw = (blockIdx.x * blockDim.x + threadIdx.x) >> 5;
    int lane = threadIdx.x & 31;
    if (gw >= NN) return;
    float kcd = d_kc[gw];
    float rsd = d_rs[gw];
    float rdg = d_rdeg[gw];
    const float4* h4 = (const float4*)h;
    float4 hv = h4[(size_t)gw * 32 + lane];
    float wg = kcd * rsd;
    float4 as = {hv.x * kcd, hv.y * kcd, hv.z * kcd, hv.w * kcd};
    float4 ag = {hv.x * wg, hv.y * wg, hv.z * wg, hv.w * wg};
    int beg = d_rp[gw], end = d_rp[gw + 1];
    for (int p = beg; p < end; p++) {
        int s = d_colsrc[p];
        float w1 = d_kc[s];
        if (w1 != 0.f) {
            float rv = d_rs[s];
            float4 hs = h4[(size_t)s * 32 + lane];
            as.x += hs.x; as.y += hs.y; as.z += hs.z; as.w += hs.w;
            ag.x = fmaf(hs.x, rv, ag.x); ag.y = fmaf(hs.y, rv, ag.y);
            ag.z = fmaf(hs.z, rv, ag.z); ag.w = fmaf(hs.w, rv, ag.w);
        }
    }
    float fg = kcd * rsd;
    as.x *= kcd; as.y *= kcd; as.z *= kcd; as.w *= kcd;
    ag.x *= fg;  ag.y *= fg;  ag.z *= fg;  ag.w *= fg;
    float4 asr = {as.x * rdg, as.y * rdg, as.z * rdg, as.w * rdg};
    size_t idx = (size_t)gw * HH + lane * 4;
    store4h(d_A + 1ULL * NPH, idx, as);
    store4h(d_A + 2ULL * NPH, idx, asr);
    store4h(d_A + 3ULL * NPH, idx, ag);
}

// ---------------- layernorm + gate + pool (reads d_Hn split fp16) -----------
__global__ void gate_kernel(float* __restrict__ h, const float* __restrict__ p0,
                            const float* __restrict__ pa) {
    int gw = (blockIdx.x * blockDim.x + threadIdx.x) >> 5;
    int lane = threadIdx.x & 31;
    if (gw >= NN) return;
    const double invc = 1.0 / ((double)NN * (double)HH);
    double md = d_stats[0] * invc;
    double vd = d_stats[1] * invc - md * md;
    float mean = (float)md;
    float inv = rsqrtf((float)vd + 1e-5f);
    size_t idx = (size_t)gw * HH + lane * 4;
    float2 fh0 = __half22float2(*(const __half2*)&d_Hn[idx]);
    float2 fh1 = __half22float2(*(const __half2*)&d_Hn[idx + 2]);
    float2 fl0 = __half22float2(*(const __half2*)&d_Hn[NPH + idx]);
    float2 fl1 = __half22float2(*(const __half2*)&d_Hn[NPH + idx + 2]);
    float4 hv = {fh0.x + fl0.x, fh0.y + fl0.y, fh1.x + fl1.x, fh1.y + fl1.y};
    float4 hn;
    hn.x = (hv.x - mean) * inv; hn.y = (hv.y - mean) * inv;
    hn.z = (hv.z - mean) * inv; hn.w = (hv.w - mean) * inv;
    float4 a = ((const float4*)p0)[lane];
    float4 b = ((const float4*)(p0 + HH))[lane];
    float d0 = hn.x * a.x + hn.y * a.y + hn.z * a.z + hn.w * a.w;
    float d1 = hn.x * b.x + hn.y * b.y + hn.z * b.z + hn.w * b.w;
#pragma unroll
    for (int o = 16; o; o >>= 1) {
        d0 += __shfl_xor_sync(0xffffffffu, d0, o);
        d1 += __shfl_xor_sync(0xffffffffu, d1, o);
    }
    float g1 = 1.f / (1.f + expf(-d0));
    float g2 = tanhf(d1);
    float gate = pa[0] * g1 + pa[1] * g2 + pa[2];
    float kv = gate > 0.01f ? 1.f : 0.f;
    float sc = gate * kv;
    hn.x *= sc; hn.y *= sc; hn.z *= sc; hn.w *= sc;
    ((float4*)h)[(size_t)gw * 32 + lane] = hn;
    store4h(d_A, idx, hn);
    if (lane == 0) d_kc[gw] *= kv;
}

// ---------------- readout ----------------------------------------------------
__global__ void readout_kernel(const float* __restrict__ h, int r) {
    int g = blockIdx.x, k = threadIdx.x;
    int b = d_gs[g], e = d_gs[g + 1];
    float s = 0.f, mx = -INFINITY;
    for (int n = b; n < e; n++) {
        float v = h[(size_t)n * HH + k];
        s += v;
        mx = fmaxf(mx, v);
    }
    float c = (float)(e - b);
    float mean = s / fmaxf(c, 1.f);
    if (e == b) mx = 0.f;
    const float* w = d_roa + r * 3;
    d_reps[((size_t)r * GG + g) * HH + k] = w[0] * mean + w[1] * mx + w[2] * s;
}

// ---------------- final head -------------------------------------------------
__global__ void final_head(const float* __restrict__ Wo, const float* __restrict__ bo,
                           const float* __restrict__ Wc, const float* __restrict__ bc,
                           float* __restrict__ out) {
    __shared__ float zr[HH];
    __shared__ float z2[HH];
    __shared__ float lg[OUTC];
    __shared__ float s_lse;
    int g = blockIdx.x, k = threadIdx.x;
    int idx = g * HH + k;
    float r0 = d_reps[idx];
    float r1 = d_reps[GG * HH + idx];
    float r2 = d_reps[2 * GG * HH + idx];
    float r3 = d_reps[3 * GG * HH + idx];
    float s = r0 + r1 + r2 + r3;
    float mx = fmaxf(fmaxf(r0, r1), fmaxf(r2, r3));
    zr[k] = d_laa[0] * eluf(s) + d_laa[1] * eluf(s * 0.25f) + d_laa[2] * eluf(mx);
    __syncthreads();
    float acc = bo[k];
    for (int k2 = 0; k2 < HH; k2++) acc = fmaf(zr[k2], Wo[k2 * HH + k], acc);
    z2[k] = eluf(acc);
    __syncthreads();
    if (k < OUTC) {
        float accl = bc[k];
        for (int k2 = 0; k2 < HH; k2++) accl = fmaf(z2[k2], Wc[k2 * OUTC + k], accl);
        lg[k] = accl;
    }
    __syncthreads();
    if (k == 0) {
        float m = lg[0];
        for (int i = 1; i < OUTC; i++) m = fmaxf(m, lg[i]);
        float se = 0.f;
        for (int i = 0; i < OUTC; i++) se += expf(lg[i] - m);
        s_lse = m + logf(se);
    }
    __syncthreads();
    if (k < OUTC) out[g * OUTC + k] = lg[k] - s_lse;
}

// ---------------- launch ------------------------------------------------------
extern "C" void kernel_launch(void* const* d_in, const int* in_sizes, int n_in,
                              void* d_out, int out_size) {
    const float* x         = (const float*)d_in[0];
    const int*   ei        = (const int*)d_in[1];
    const int*   batch     = (const int*)d_in[2];
    const float* lin1_W    = (const float*)d_in[3];
    const float* lin1_b    = (const float*)d_in[4];
    const float* gnn_W     = (const float*)d_in[5];
    const float* pool_p    = (const float*)d_in[6];
    const float* lin_out_W = (const float*)d_in[7];
    const float* lin_out_b = (const float*)d_in[8];
    const float* cls_W     = (const float*)d_in[9];
    const float* cls_b     = (const float*)d_in[10];
    const float* na_log    = (const float*)d_in[11];
    const float* pool_log  = (const float*)d_in[12];
    const float* ro_log    = (const float*)d_in[13];
    const float* la_log    = (const float*)d_in[14];
    float* out = (float*)d_out;

    float *bufA, *bufB, *naa, *pa;
    __half *Ab, *Hnb, *Bb, *B1b;
    cudaGetSymbolAddress((void**)&bufA, d_bufA);
    cudaGetSymbolAddress((void**)&bufB, d_bufB);
    cudaGetSymbolAddress((void**)&naa, d_naa);
    cudaGetSymbolAddress((void**)&pa, d_pa);
    cudaGetSymbolAddress((void**)&Ab, d_A);
    cudaGetSymbolAddress((void**)&Hnb, d_Hn);
    cudaGetSymbolAddress((void**)&Bb, d_B);
    cudaGetSymbolAddress((void**)&B1b, d_B1);

    cudaFuncSetAttribute(gemm_mma<4, 0>, cudaFuncAttributeMaxDynamicSharedMemorySize, SM_TOTAL);
    cudaFuncSetAttribute(gemm_mma<16, 1>, cudaFuncAttributeMaxDynamicSharedMemorySize, SM_TOTAL);

    const int GB = ((NN + 127) / 128) * 2;   // 782
    const int EB = (EE + 255) / 256;
    const int WB = (NN * 32 + 255) / 256;
    const int NBK = (NN + 255) / 256;

    setup_kernel<<<NBK, 256>>>(batch, na_log, pool_log, ro_log, la_log);
    convert_kernel<<<(NHTOT + HSQ + 255) / 256, 256>>>(x, lin1_W);
    csr_count<<<EB, 256>>>(ei);
    // launch #4 = profiled slot: lin1 GEMM
    gemm_mma<4, 0><<<GB, 256, SM_TOTAL>>>(Hnb, B1b, bufA, Ab, lin1_b);
    scan1<<<NBK, 256>>>();
    scan2<<<1, 256>>>();
    scan3<<<NBK, 256>>>();
    csr_fill<<<EB, 256>>>(ei);
    readout_kernel<<<GG, HH>>>(bufA, 0);

    float* hcur = bufA;
    float* hnew = bufB;
    for (int i = 0; i < LL; i++) {
        const float* Wi = gnn_W + (size_t)i * 6 * HSQ;
        combine_deg<<<(4 * HSQ + NN + 255) / 256, 256>>>(Wi, naa + i * 4);
        aggregate_kernel<<<WB, 256>>>(hcur);
        gemm_mma<16, 1><<<GB, 256, SM_TOTAL>>>(Ab, Bb, nullptr, Hnb, nullptr);
        gate_kernel<<<WB, 256>>>(hnew, pool_p + (size_t)i * 2 * HH, pa + i * 3);
        readout_kernel<<<GG, HH>>>(hnew, i + 1);
        float* t = hcur; hcur = hnew; hnew = t;
    }

    final_head<<<GG, HH>>>(lin_out_W, lin_out_b, cls_W, cls_b, out);
}